// round 12
// baseline (speedup 1.0000x reference)
#include <cuda_runtime.h>
#include <cstdint>

#define NPIX (512*512)

// Shared layout (float indices). X/H row stride = 36 floats (144B):
// A-fragment lds banks = (36r + c) % 32 = (4r + c) % 32 -> all 32 lanes
// distinct (r=lane>>2 in 0..7, c=lane&3 in 0..3): conflict-free.
#define F_XH 0
#define F_XL 4608
#define F_HH 9216
#define F_HL 13824
#define F_BF 18432   // B-fragment table: float2[2048] (layer,ver,kt,nt,lane)
#define F_ZF 22528   // zf[8][32]
#define F_B1 22784
#define F_B2 22816
#define F_W3 22848
#define F_B3 22880
#define SMEM_BYTES (22884 * 4)

__device__ __forceinline__ uint32_t sptr(const void* p) {
    return (uint32_t)__cvta_generic_to_shared(p);
}
__device__ __forceinline__ float tf32_rna(float x) {
    uint32_t r;
    asm("cvt.rna.tf32.f32 %0, %1;" : "=r"(r) : "f"(x));
    return __uint_as_float(r);
}
// Volatile shared accesses: anti-hoist (prevents weight->register promotion
// spills; the protection every passing round has relied on).
__device__ __forceinline__ uint32_t lds32v(uint32_t a) {
    uint32_t v;
    asm volatile("ld.shared.b32 %0, [%1];" : "=r"(v) : "r"(a));
    return v;
}
__device__ __forceinline__ void lds64v(uint32_t a, uint32_t& v0, uint32_t& v1) {
    asm volatile("ld.shared.v2.b32 {%0, %1}, [%2];" : "=r"(v0), "=r"(v1) : "r"(a));
}
__device__ __forceinline__ float2 ldsf2v(uint32_t a) {
    float2 v;
    asm volatile("ld.shared.v2.f32 {%0, %1}, [%2];" : "=f"(v.x), "=f"(v.y) : "r"(a));
    return v;
}
__device__ __forceinline__ float4 ldsf4v(uint32_t a) {
    float4 v;
    asm volatile("ld.shared.v4.f32 {%0, %1, %2, %3}, [%4];"
                 : "=f"(v.x), "=f"(v.y), "=f"(v.z), "=f"(v.w) : "r"(a));
    return v;
}
__device__ __forceinline__ void sts64v(uint32_t a, float v0, float v1) {
    asm volatile("st.shared.v2.f32 [%0], {%1, %2};" :: "r"(a), "f"(v0), "f"(v1));
}
__device__ __forceinline__ void sts128v(uint32_t a, float4 v) {
    asm volatile("st.shared.v4.f32 [%0], {%1, %2, %3, %4};"
                 :: "r"(a), "f"(v.x), "f"(v.y), "f"(v.z), "f"(v.w));
}

// Warp-level tensor-core MMA (HMMA path; plain sm_80+ PTX, not 'a'-gated).
__device__ __forceinline__ void mma_tf32(float* d, const uint32_t* a,
                                         uint32_t b0, uint32_t b1) {
    asm volatile(
        "mma.sync.aligned.m16n8k8.row.col.f32.tf32.tf32.f32 "
        "{%0,%1,%2,%3}, {%4,%5,%6,%7}, {%8,%9}, {%0,%1,%2,%3};"
        : "+f"(d[0]), "+f"(d[1]), "+f"(d[2]), "+f"(d[3])
        : "r"(a[0]), "r"(a[1]), "r"(a[2]), "r"(a[3]), "r"(b0), "r"(b1));
}

// One 3xTF32 [32x32x32] warp GEMM. aH/aL: byte addrs of this warp's 32-row
// hi/lo A block (stride 144B). bfL: byte addr of this layer's B-frag table.
__device__ __forceinline__ void warp_gemm3x(uint32_t aH, uint32_t aL,
                                            uint32_t bfL, int lane, float* d) {
    const int g = lane >> 2, tig = lane & 3;
    #pragma unroll
    for (int kt = 0; kt < 4; kt++) {
        uint32_t ah[2][4], al[2][4];
        const uint32_t cb = (kt * 8 + tig) * 4;
        #pragma unroll
        for (int mt = 0; mt < 2; mt++) {
            const uint32_t r0 = (mt * 16 + g) * 144;
            ah[mt][0] = lds32v(aH + r0 + cb);
            ah[mt][1] = lds32v(aH + r0 + 8 * 144 + cb);
            ah[mt][2] = lds32v(aH + r0 + cb + 16);
            ah[mt][3] = lds32v(aH + r0 + 8 * 144 + cb + 16);
            al[mt][0] = lds32v(aL + r0 + cb);
            al[mt][1] = lds32v(aL + r0 + 8 * 144 + cb);
            al[mt][2] = lds32v(aL + r0 + cb + 16);
            al[mt][3] = lds32v(aL + r0 + 8 * 144 + cb + 16);
        }
        #pragma unroll
        for (int nt = 0; nt < 4; nt++) {
            uint32_t bh0, bh1, bl0, bl1;
            lds64v(bfL + (uint32_t)(((0 * 16 + kt * 4 + nt) * 32 + lane) * 8), bh0, bh1);
            lds64v(bfL + (uint32_t)(((1 * 16 + kt * 4 + nt) * 32 + lane) * 8), bl0, bl1);
            #pragma unroll
            for (int mt = 0; mt < 2; mt++) {
                float* dd = d + (mt * 4 + nt) * 4;
                mma_tf32(dd, ah[mt], bh0, bh1);   // hi*hi
                mma_tf32(dd, al[mt], bh0, bh1);   // lo*hi
                mma_tf32(dd, ah[mt], bl0, bl1);   // hi*lo
            }
        }
    }
}

__global__ __launch_bounds__(128) void g_tensor3d_mma(
    const float* __restrict__ z,
    const float* __restrict__ data,
    const float* __restrict__ z_data,
    const float* __restrict__ lerp,
    const int*   __restrict__ x0,
    const int*   __restrict__ y0,
    const int*   __restrict__ x1,
    const int*   __restrict__ y1,
    const float* __restrict__ W1,
    const float* __restrict__ b1,
    const float* __restrict__ W2,
    const float* __restrict__ b2,
    const float* __restrict__ W3,
    const float* __restrict__ b3,
    float*       __restrict__ out)
{
    extern __shared__ float smem[];
    const uint32_t sb = sptr(smem);
    const int tid = threadIdx.x;
    const int lane = tid & 31;
    const int g = lane >> 2, tig = lane & 3;
    const int warpRow = (tid >> 5) * 32;

    // ---- Init: B-fragment table (lane-major, conflict-free reload) ----
    // entry e: lane, nt, kt, ver(hi/lo), layer. float2 = (W[k0][n], W[k0+4][n])
    // matching mma.m16n8k8 "col" B-fragment (b0,b1) for this lane.
    #pragma unroll
    for (int e = 0; e < 16; e++) {
        const int idx = e * 128 + tid;
        const int ln = idx & 31;
        const int q  = idx >> 5;
        const int nt = q & 3, kt = (q >> 2) & 3, ver = (q >> 4) & 1, layer = q >> 5;
        const int k0 = kt * 8 + (ln & 3);
        const int n  = nt * 8 + (ln >> 2);
        const float* W = layer ? W2 : W1;
        const float w0 = W[k0 * 32 + n];
        const float w1 = W[(k0 + 4) * 32 + n];
        float f0, f1;
        if (ver == 0) { f0 = tf32_rna(w0); f1 = tf32_rna(w1); }
        else          { f0 = tf32_rna(w0 - tf32_rna(w0)); f1 = tf32_rna(w1 - tf32_rna(w1)); }
        float2 t; t.x = f0; t.y = f1;
        *(float2*)(smem + F_BF + idx * 2) = t;
    }
    // z features zf[8][32].
    #pragma unroll
    for (int k = 0; k < 2; k++) {
        const int t = tid + 128 * k;
        const int b = t >> 5, i = t & 31;
        const float zn = 63.0f * z[b];
        int z0i = (int)zn;
        if (z0i < 0) z0i = 0;
        if (z0i > 63) z0i = 63;
        int z1i = z0i + 1;
        if (z1i > 63) z1i = 63;
        const float zl = zn - truncf(zn);
        smem[F_ZF + b * 32 + i] =
            z_data[z0i * 32 + i] * (1.0f - zl) + z_data[z1i * 32 + i] * zl;
    }
    if (tid < 32) {
        smem[F_B1 + tid] = b1[tid];
        smem[F_B2 + tid] = b2[tid];
        smem[F_W3 + tid] = W3[tid];
    }
    if (tid == 0) smem[F_B3] = b3[0];

    // ---- Bilinear gather -> xy[32] registers ----
    const int pixbase = blockIdx.x * 128;
    const int p = pixbase + tid;
    const float wx = lerp[2 * p + 0];
    const float wy = lerp[2 * p + 1];
    const int ix0 = x0[p], iy0 = y0[p], ix1 = x1[p], iy1 = y1[p];
    const float4* p00 = (const float4*)(data + (iy0 * 512 + ix0) * 32);
    const float4* p10 = (const float4*)(data + (iy0 * 512 + ix1) * 32);
    const float4* p01 = (const float4*)(data + (iy1 * 512 + ix0) * 32);
    const float4* p11 = (const float4*)(data + (iy1 * 512 + ix1) * 32);
    const float w00 = (1.0f - wx) * (1.0f - wy);
    const float w10 = wx * (1.0f - wy);
    const float w01 = (1.0f - wx) * wy;
    const float w11 = wx * wy;
    float xy[32];
    #pragma unroll
    for (int q = 0; q < 8; q++) {
        const float4 a = p00[q];
        const float4 c = p10[q];
        const float4 e = p01[q];
        const float4 gg = p11[q];
        xy[4 * q + 0] = a.x * w00 + c.x * w10 + e.x * w01 + gg.x * w11;
        xy[4 * q + 1] = a.y * w00 + c.y * w10 + e.y * w01 + gg.y * w11;
        xy[4 * q + 2] = a.z * w00 + c.z * w10 + e.z * w01 + gg.z * w11;
        xy[4 * q + 3] = a.w * w00 + c.w * w10 + e.w * w01 + gg.w * w11;
    }
    __syncthreads();   // only block-wide sync: tables ready

    const float b3v = smem[F_B3];
    const uint32_t aXH = sb + F_XH * 4 + warpRow * 144;
    const uint32_t aXL = sb + F_XL * 4 + warpRow * 144;
    const uint32_t aHH = sb + F_HH * 4 + warpRow * 144;
    const uint32_t aHL = sb + F_HL * 4 + warpRow * 144;
    const uint32_t myXH = sb + F_XH * 4 + tid * 144;   // this thread's row
    const uint32_t myXL = sb + F_XL * 4 + tid * 144;
    const uint32_t bf1 = sb + F_BF * 4;
    const uint32_t bf2 = sb + F_BF * 4 + 16384 / 2;    // layer-2 half (1024 float2)

    #pragma unroll 1
    for (int b = 0; b < 8; b++) {
        // ---- Build X_b = xy .* zf_b, split hi/lo (warp-local rows) ----
        __syncwarp();   // WAR: prior GEMM1 reads of X finished
        #pragma unroll
        for (int q = 0; q < 8; q++) {
            const float4 zf = ldsf4v(sb + (F_ZF + b * 32 + q * 4) * 4);
            const float v0 = xy[4 * q + 0] * zf.x;
            const float v1 = xy[4 * q + 1] * zf.y;
            const float v2 = xy[4 * q + 2] * zf.z;
            const float v3 = xy[4 * q + 3] * zf.w;
            float4 hv, lv;
            hv.x = tf32_rna(v0); lv.x = tf32_rna(v0 - hv.x);
            hv.y = tf32_rna(v1); lv.y = tf32_rna(v1 - hv.y);
            hv.z = tf32_rna(v2); lv.z = tf32_rna(v2 - hv.z);
            hv.w = tf32_rna(v3); lv.w = tf32_rna(v3 - hv.w);
            sts128v(myXH + q * 16, hv);
            sts128v(myXL + q * 16, lv);
        }
        __syncwarp();

        // ---- Layer 1 GEMM ----
        float d1[32];
        #pragma unroll
        for (int m = 0; m < 32; m++) d1[m] = 0.0f;
        warp_gemm3x(aXH, aXL, bf1, lane, d1);

        // ---- Epilogue 1: relu(d1 + b1) -> H hi/lo ----
        __syncwarp();   // WAR: prior GEMM2 reads of H finished
        #pragma unroll
        for (int nt = 0; nt < 4; nt++) {
            const float2 bp = ldsf2v(sb + (F_B1 + nt * 8 + 2 * tig) * 4);
            #pragma unroll
            for (int mt = 0; mt < 2; mt++) {
                const float* dd = d1 + (mt * 4 + nt) * 4;
                const uint32_t r0 = (mt * 16 + g) * 144 + (nt * 8 + 2 * tig) * 4;
                {
                    const float v0 = fmaxf(dd[0] + bp.x, 0.0f);
                    const float v1 = fmaxf(dd[1] + bp.y, 0.0f);
                    const float h0 = tf32_rna(v0), h1v = tf32_rna(v1);
                    sts64v(aHH + r0, h0, h1v);
                    sts64v(aHL + r0, tf32_rna(v0 - h0), tf32_rna(v1 - h1v));
                }
                {
                    const float v0 = fmaxf(dd[2] + bp.x, 0.0f);
                    const float v1 = fmaxf(dd[3] + bp.y, 0.0f);
                    const float h0 = tf32_rna(v0), h1v = tf32_rna(v1);
                    sts64v(aHH + r0 + 8 * 144, h0, h1v);
                    sts64v(aHL + r0 + 8 * 144, tf32_rna(v0 - h0), tf32_rna(v1 - h1v));
                }
            }
        }
        __syncwarp();

        // ---- Layer 2 GEMM ----
        float d2[32];
        #pragma unroll
        for (int m = 0; m < 32; m++) d2[m] = 0.0f;
        warp_gemm3x(aHH, aHL, bf2, lane, d2);

        // ---- Epilogue 2: relu(d2 + b2) . W3, cross-lane reduce, store ----
        float pr[4] = {0.0f, 0.0f, 0.0f, 0.0f};
        #pragma unroll
        for (int nt = 0; nt < 4; nt++) {
            const float2 bp = ldsf2v(sb + (F_B2 + nt * 8 + 2 * tig) * 4);
            const float2 wp = ldsf2v(sb + (F_W3 + nt * 8 + 2 * tig) * 4);
            #pragma unroll
            for (int mt = 0; mt < 2; mt++) {
                const float* dd = d2 + (mt * 4 + nt) * 4;
                pr[mt * 2 + 0] = fmaf(fmaxf(dd[0] + bp.x, 0.0f), wp.x,
                                 fmaf(fmaxf(dd[1] + bp.y, 0.0f), wp.y, pr[mt * 2 + 0]));
                pr[mt * 2 + 1] = fmaf(fmaxf(dd[2] + bp.x, 0.0f), wp.x,
                                 fmaf(fmaxf(dd[3] + bp.y, 0.0f), wp.y, pr[mt * 2 + 1]));
            }
        }
        #pragma unroll
        for (int m = 0; m < 4; m++) {
            pr[m] += __shfl_xor_sync(0xFFFFFFFFu, pr[m], 1);
            pr[m] += __shfl_xor_sync(0xFFFFFFFFu, pr[m], 2);
        }
        if (tig == 0) {
            float* ob = out + b * NPIX + pixbase + warpRow;
            ob[0 * 16 + g]     = pr[0] + b3v;
            ob[0 * 16 + g + 8] = pr[1] + b3v;
            ob[1 * 16 + g]     = pr[2] + b3v;
            ob[1 * 16 + g + 8] = pr[3] + b3v;
        }
    }
}

extern "C" void kernel_launch(void* const* d_in, const int* in_sizes, int n_in,
                              void* d_out, int out_size) {
    const float* z      = (const float*)d_in[0];
    const float* data   = (const float*)d_in[1];
    const float* z_data = (const float*)d_in[2];
    const float* lerp   = (const float*)d_in[3];
    const int*   x0     = (const int*)d_in[4];
    const int*   y0     = (const int*)d_in[5];
    const int*   x1     = (const int*)d_in[6];
    const int*   y1     = (const int*)d_in[7];
    const float* W1     = (const float*)d_in[8];
    const float* b1     = (const float*)d_in[9];
    const float* W2     = (const float*)d_in[10];
    const float* b2     = (const float*)d_in[11];
    const float* W3     = (const float*)d_in[12];
    const float* b3     = (const float*)d_in[13];
    float* out = (float*)d_out;

    cudaFuncSetAttribute(g_tensor3d_mma,
                         cudaFuncAttributeMaxDynamicSharedMemorySize, SMEM_BYTES);

    g_tensor3d_mma<<<NPIX / 128, 128, SMEM_BYTES>>>(z, data, z_data, lerp,
                                                    x0, y0, x1, y1,
                                                    W1, b1, W2, b2, W3, b3, out);
}

// round 13
// speedup vs baseline: 1.5775x; 1.5775x over previous
#include <cuda_runtime.h>
#include <cstdint>

#define NPIX (512*512)

// SMEM byte offsets.
// A area: per-warp [X 4608B][H 4608B], warp stride 9216, 4 warps = 36864.
// A-block row = 144B (128B data + 16B pad): 4 chunks x 32B; chunk t holds
// word-pairs (hi_j, lo_j) for j=0..3 where word j = bf16x2 of cols (2t+8j, 2t+8j+1).
#define OFF_A   0
#define OFF_B   36864   // B frag table: 2 layers x 8 (kt,nt) x 32 lanes x 16B = 8192
#define OFF_ZF  45056   // zf[8][32] f32
#define OFF_B1  46080
#define OFF_B2  46208
#define OFF_W3  46336
#define OFF_B3  46464
#define SMEM_BYTES 46592

#define ROWSTR 144

__device__ __forceinline__ uint32_t sptr(const void* p) {
    return (uint32_t)__cvta_generic_to_shared(p);
}
// pack (lo, hi) floats -> bf16x2 (lo in low half)
__device__ __forceinline__ uint32_t pkbf2(float lo, float hi) {
    uint32_t d;
    asm("cvt.rn.bf16x2.f32 %0, %1, %2;" : "=r"(d) : "f"(hi), "f"(lo));
    return d;
}
__device__ __forceinline__ float lo16f(uint32_t p) { return __uint_as_float(p << 16); }
__device__ __forceinline__ float hi16f(uint32_t p) { return __uint_as_float(p & 0xFFFF0000u); }

// Volatile shared accesses: anti-hoist (prevents weight->register promotion
// spills) and keeps loads at their use sites.
__device__ __forceinline__ uint4 lds128u(uint32_t a) {
    uint4 v;
    asm volatile("ld.shared.v4.b32 {%0,%1,%2,%3}, [%4];"
                 : "=r"(v.x), "=r"(v.y), "=r"(v.z), "=r"(v.w) : "r"(a));
    return v;
}
__device__ __forceinline__ float2 ldsf2v(uint32_t a) {
    float2 v;
    asm volatile("ld.shared.v2.f32 {%0, %1}, [%2];" : "=f"(v.x), "=f"(v.y) : "r"(a));
    return v;
}
__device__ __forceinline__ float4 ldsf4v(uint32_t a) {
    float4 v;
    asm volatile("ld.shared.v4.f32 {%0, %1, %2, %3}, [%4];"
                 : "=f"(v.x), "=f"(v.y), "=f"(v.z), "=f"(v.w) : "r"(a));
    return v;
}
__device__ __forceinline__ void sts128u(uint32_t a, uint4 v) {
    asm volatile("st.shared.v4.b32 [%0], {%1,%2,%3,%4};"
                 :: "r"(a), "r"(v.x), "r"(v.y), "r"(v.z), "r"(v.w));
}
__device__ __forceinline__ void sts64u(uint32_t a, uint32_t v0, uint32_t v1) {
    asm volatile("st.shared.v2.b32 [%0], {%1, %2};" :: "r"(a), "r"(v0), "r"(v1));
}

// Tensor-core MMA, bf16 m16n8k16 (plain sm_80+ PTX; not 'a'-gated).
__device__ __forceinline__ void mma_bf16(float* d, const uint32_t* a,
                                         uint32_t b0, uint32_t b1) {
    asm volatile(
        "mma.sync.aligned.m16n8k16.row.col.f32.bf16.bf16.f32 "
        "{%0,%1,%2,%3}, {%4,%5,%6,%7}, {%8,%9}, {%0,%1,%2,%3};"
        : "+f"(d[0]), "+f"(d[1]), "+f"(d[2]), "+f"(d[3])
        : "r"(a[0]), "r"(a[1]), "r"(a[2]), "r"(a[3]), "r"(b0), "r"(b1));
}

// One 3x-bf16-split [32x32x32] warp GEMM. aBase = this warp's A block,
// bBase = layer's B table. d = [mt][nt][4] fp32 accumulators.
__device__ __forceinline__ void wgemm(uint32_t aBase, uint32_t bBase,
                                      int lane, float* d) {
    const int g = lane >> 2, t = lane & 3;
    #pragma unroll
    for (int mt = 0; mt < 2; mt++) {
        const uint32_t r0 = aBase + (mt * 16 + g) * ROWSTR + t * 32;
        const uint32_t r1 = aBase + (mt * 16 + g + 8) * ROWSTR + t * 32;
        const uint4 A0k0 = lds128u(r0);        // a0hi, a0lo, a2hi, a2lo (kt=0)
        const uint4 A1k0 = lds128u(r1);        // a1hi, a1lo, a3hi, a3lo (kt=0)
        const uint4 A0k1 = lds128u(r0 + 16);   // kt=1
        const uint4 A1k1 = lds128u(r1 + 16);
        const uint32_t ah0[4] = {A0k0.x, A1k0.x, A0k0.z, A1k0.z};
        const uint32_t al0[4] = {A0k0.y, A1k0.y, A0k0.w, A1k0.w};
        const uint32_t ah1[4] = {A0k1.x, A1k1.x, A0k1.z, A1k1.z};
        const uint32_t al1[4] = {A0k1.y, A1k1.y, A0k1.w, A1k1.w};
        #pragma unroll
        for (int kt = 0; kt < 2; kt++) {
            const uint32_t* ah = kt ? ah1 : ah0;
            const uint32_t* al = kt ? al1 : al0;
            #pragma unroll
            for (int nt = 0; nt < 4; nt++) {
                const uint4 bv = lds128u(bBase + (((kt * 4 + nt) * 32) + lane) * 16);
                float* dd = d + (mt * 4 + nt) * 4;
                mma_bf16(dd, ah, bv.x, bv.y);   // hi*hi
                mma_bf16(dd, al, bv.x, bv.y);   // lo*hi
                mma_bf16(dd, ah, bv.z, bv.w);   // hi*lo
            }
        }
    }
}

__global__ __launch_bounds__(128, 3) void g_tensor3d_mma(
    const float* __restrict__ z,
    const float* __restrict__ data,
    const float* __restrict__ z_data,
    const float* __restrict__ lerp,
    const int*   __restrict__ x0,
    const int*   __restrict__ y0,
    const int*   __restrict__ x1,
    const int*   __restrict__ y1,
    const float* __restrict__ W1,
    const float* __restrict__ b1,
    const float* __restrict__ W2,
    const float* __restrict__ b2,
    const float* __restrict__ W3,
    const float* __restrict__ b3,
    float*       __restrict__ out)
{
    extern __shared__ float smem[];
    const uint32_t sb = sptr(smem);
    const int tid = threadIdx.x;
    const int lane = tid & 31;
    const int warp = tid >> 5;
    const int g = lane >> 2, t = lane & 3;

    // ---- Init: B fragment table (hi/lo combined 16B entries, lane-major) ----
    #pragma unroll
    for (int it = 0; it < 4; it++) {
        const int s = it * 128 + tid;       // 0..511
        const int ln = s & 31;
        const int e = s >> 5;               // 0..15
        const int nt = e & 3, kt = (e >> 2) & 1, layer = (e >> 3) & 1;
        const int lg = ln >> 2, lt = ln & 3;
        const int k0 = 16 * kt + 2 * lt;
        const int n  = 8 * nt + lg;
        const float* W = layer ? W2 : W1;
        const float wa = W[k0 * 32 + n];
        const float wb = W[(k0 + 1) * 32 + n];
        const float wc = W[(k0 + 8) * 32 + n];
        const float wd = W[(k0 + 9) * 32 + n];
        const uint32_t bh0 = pkbf2(wa, wb);
        const uint32_t bh1 = pkbf2(wc, wd);
        const uint32_t bl0 = pkbf2(wa - lo16f(bh0), wb - hi16f(bh0));
        const uint32_t bl1 = pkbf2(wc - lo16f(bh1), wd - hi16f(bh1));
        uint4 v; v.x = bh0; v.y = bh1; v.z = bl0; v.w = bl1;
        *(uint4*)((char*)smem + OFF_B + s * 16) = v;
    }
    // z features zf[8][32].
    #pragma unroll
    for (int k = 0; k < 2; k++) {
        const int tt = tid + 128 * k;
        const int b = tt >> 5, i = tt & 31;
        const float zn = 63.0f * z[b];
        int z0i = (int)zn;
        if (z0i < 0) z0i = 0;
        if (z0i > 63) z0i = 63;
        int z1i = z0i + 1;
        if (z1i > 63) z1i = 63;
        const float zl = zn - truncf(zn);
        *(float*)((char*)smem + OFF_ZF + (b * 32 + i) * 4) =
            z_data[z0i * 32 + i] * (1.0f - zl) + z_data[z1i * 32 + i] * zl;
    }
    if (tid < 32) {
        *(float*)((char*)smem + OFF_B1 + tid * 4) = b1[tid];
        *(float*)((char*)smem + OFF_B2 + tid * 4) = b2[tid];
        *(float*)((char*)smem + OFF_W3 + tid * 4) = W3[tid];
    }
    if (tid == 0) *(float*)((char*)smem + OFF_B3) = b3[0];

    // ---- Bilinear gather -> xy[32] registers ----
    const int pixbase = blockIdx.x * 128;
    const int p = pixbase + tid;
    const float wx = lerp[2 * p + 0];
    const float wy = lerp[2 * p + 1];
    const int ix0 = x0[p], iy0 = y0[p], ix1 = x1[p], iy1 = y1[p];
    const float4* p00 = (const float4*)(data + (iy0 * 512 + ix0) * 32);
    const float4* p10 = (const float4*)(data + (iy0 * 512 + ix1) * 32);
    const float4* p01 = (const float4*)(data + (iy1 * 512 + ix0) * 32);
    const float4* p11 = (const float4*)(data + (iy1 * 512 + ix1) * 32);
    const float w00 = (1.0f - wx) * (1.0f - wy);
    const float w10 = wx * (1.0f - wy);
    const float w01 = (1.0f - wx) * wy;
    const float w11 = wx * wy;
    float xy[32];
    #pragma unroll
    for (int q = 0; q < 8; q++) {
        const float4 a = p00[q];
        const float4 c = p10[q];
        const float4 e = p01[q];
        const float4 gg = p11[q];
        xy[4 * q + 0] = a.x * w00 + c.x * w10 + e.x * w01 + gg.x * w11;
        xy[4 * q + 1] = a.y * w00 + c.y * w10 + e.y * w01 + gg.y * w11;
        xy[4 * q + 2] = a.z * w00 + c.z * w10 + e.z * w01 + gg.z * w11;
        xy[4 * q + 3] = a.w * w00 + c.w * w10 + e.w * w01 + gg.w * w11;
    }
    __syncthreads();   // tables ready

    const float b3v = *(const float*)((char*)smem + OFF_B3);
    const uint32_t aX  = sb + OFF_A + warp * 9216;
    const uint32_t aH  = aX + 4608;
    const uint32_t myX = aX + lane * ROWSTR;   // this thread's X row
    const uint32_t bL1 = sb + OFF_B;
    const uint32_t bL2 = sb + OFF_B + 4096;

    #pragma unroll 1
    for (int b = 0; b < 8; b++) {
        // ---- Build X_b = xy .* zf_b, bf16 hi/lo interleaved layout ----
        __syncwarp();   // WAR vs previous gemm1 reads
        {
            float zf[32];
            #pragma unroll
            for (int q = 0; q < 8; q++) {
                const float4 v = ldsf4v(sb + OFF_ZF + b * 128 + q * 16);
                zf[4 * q + 0] = v.x; zf[4 * q + 1] = v.y;
                zf[4 * q + 2] = v.z; zf[4 * q + 3] = v.w;
            }
            #pragma unroll
            for (int c = 0; c < 4; c++) {
                uint32_t hw[4], lw[4];
                #pragma unroll
                for (int j = 0; j < 4; j++) {
                    const int col = 2 * c + 8 * j;
                    const float v0 = xy[col] * zf[col];
                    const float v1 = xy[col + 1] * zf[col + 1];
                    const uint32_t hp = pkbf2(v0, v1);
                    hw[j] = hp;
                    lw[j] = pkbf2(v0 - lo16f(hp), v1 - hi16f(hp));
                }
                uint4 w1v; w1v.x = hw[0]; w1v.y = lw[0]; w1v.z = hw[1]; w1v.w = lw[1];
                uint4 w2v; w2v.x = hw[2]; w2v.y = lw[2]; w2v.z = hw[3]; w2v.w = lw[3];
                sts128u(myX + c * 32, w1v);
                sts128u(myX + c * 32 + 16, w2v);
            }
        }
        __syncwarp();

        // ---- Layer 1 GEMM ----
        float d1[32];
        #pragma unroll
        for (int m = 0; m < 32; m++) d1[m] = 0.0f;
        wgemm(aX, bL1, lane, d1);

        // ---- Epilogue 1: H = relu(d1 + b1), hi/lo split, fragment-direct ----
        __syncwarp();   // WAR vs previous gemm2 reads
        #pragma unroll
        for (int nt = 0; nt < 4; nt++) {
            const float2 bb = ldsf2v(sb + OFF_B1 + (nt * 8 + 2 * t) * 4);
            #pragma unroll
            for (int mt = 0; mt < 2; mt++) {
                const float* dd = d1 + (mt * 4 + nt) * 4;
                {
                    const float v0 = fmaxf(dd[0] + bb.x, 0.0f);
                    const float v1 = fmaxf(dd[1] + bb.y, 0.0f);
                    const uint32_t hp = pkbf2(v0, v1);
                    const uint32_t lp = pkbf2(v0 - lo16f(hp), v1 - hi16f(hp));
                    sts64u(aH + (mt * 16 + g) * ROWSTR + t * 32 + nt * 8, hp, lp);
                }
                {
                    const float v0 = fmaxf(dd[2] + bb.x, 0.0f);
                    const float v1 = fmaxf(dd[3] + bb.y, 0.0f);
                    const uint32_t hp = pkbf2(v0, v1);
                    const uint32_t lp = pkbf2(v0 - lo16f(hp), v1 - hi16f(hp));
                    sts64u(aH + (mt * 16 + g + 8) * ROWSTR + t * 32 + nt * 8, hp, lp);
                }
            }
        }
        __syncwarp();

        // ---- Layer 2 GEMM ----
        float d2[32];
        #pragma unroll
        for (int m = 0; m < 32; m++) d2[m] = 0.0f;
        wgemm(aH, bL2, lane, d2);

        // ---- Epilogue 2: relu(d2 + b2) . W3, cross-lane reduce, store ----
        float pr[4] = {0.0f, 0.0f, 0.0f, 0.0f};
        #pragma unroll
        for (int nt = 0; nt < 4; nt++) {
            const float2 bp = ldsf2v(sb + OFF_B2 + (nt * 8 + 2 * t) * 4);
            const float2 wp = ldsf2v(sb + OFF_W3 + (nt * 8 + 2 * t) * 4);
            #pragma unroll
            for (int mt = 0; mt < 2; mt++) {
                const float* dd = d2 + (mt * 4 + nt) * 4;
                pr[mt * 2 + 0] = fmaf(fmaxf(dd[0] + bp.x, 0.0f), wp.x,
                                 fmaf(fmaxf(dd[1] + bp.y, 0.0f), wp.y, pr[mt * 2 + 0]));
                pr[mt * 2 + 1] = fmaf(fmaxf(dd[2] + bp.x, 0.0f), wp.x,
                                 fmaf(fmaxf(dd[3] + bp.y, 0.0f), wp.y, pr[mt * 2 + 1]));
            }
        }
        #pragma unroll
        for (int m = 0; m < 4; m++) {
            pr[m] += __shfl_xor_sync(0xFFFFFFFFu, pr[m], 1);
            pr[m] += __shfl_xor_sync(0xFFFFFFFFu, pr[m], 2);
        }
        if (t == 0) {
            float* ob = out + b * NPIX + pixbase + warp * 32;
            ob[g]          = pr[0] + b3v;
            ob[g + 8]      = pr[1] + b3v;
            ob[16 + g]     = pr[2] + b3v;
            ob[16 + g + 8] = pr[3] + b3v;
        }
    }
}

extern "C" void kernel_launch(void* const* d_in, const int* in_sizes, int n_in,
                              void* d_out, int out_size) {
    const float* z      = (const float*)d_in[0];
    const float* data   = (const float*)d_in[1];
    const float* z_data = (const float*)d_in[2];
    const float* lerp   = (const float*)d_in[3];
    const int*   x0     = (const int*)d_in[4];
    const int*   y0     = (const int*)d_in[5];
    const int*   x1     = (const int*)d_in[6];
    const int*   y1     = (const int*)d_in[7];
    const float* W1     = (const float*)d_in[8];
    const float* b1     = (const float*)d_in[9];
    const float* W2     = (const float*)d_in[10];
    const float* b2     = (const float*)d_in[11];
    const float* W3     = (const float*)d_in[12];
    const float* b3     = (const float*)d_in[13];
    float* out = (float*)d_out;

    cudaFuncSetAttribute(g_tensor3d_mma,
                         cudaFuncAttributeMaxDynamicSharedMemorySize, SMEM_BYTES);

    g_tensor3d_mma<<<NPIX / 128, 128, SMEM_BYTES>>>(z, data, z_data, lerp,
                                                    x0, y0, x1, y1,
                                                    W1, b1, W2, b2, W3, b3, out);
}

// round 14
// speedup vs baseline: 1.7637x; 1.1180x over previous
#include <cuda_runtime.h>
#include <cstdint>

#define NPIX (512*512)

// SMEM byte offsets.
// A area: per-warp [X 4608B][H 4608B], warp stride 9216, 4 warps = 36864.
// A-block row = 144B (128B data + 16B pad): 4 chunks x 32B; chunk t holds
// word-pairs (hi_j, lo_j) for j=0..3 where word j = bf16x2 of cols (2t+8j, 2t+8j+1).
#define OFF_A   0
#define OFF_B   36864   // B frag table (init only; consumed into registers)
#define OFF_ZF  45056   // zf[8][32] f32
#define OFF_B1  46080
#define OFF_B2  46208
#define OFF_W3  46336
#define OFF_B3  46464
#define SMEM_BYTES 46592

#define ROWSTR 144

__device__ __forceinline__ uint32_t sptr(const void* p) {
    return (uint32_t)__cvta_generic_to_shared(p);
}
// pack (lo, hi) floats -> bf16x2 (lo in low half)
__device__ __forceinline__ uint32_t pkbf2(float lo, float hi) {
    uint32_t d;
    asm("cvt.rn.bf16x2.f32 %0, %1, %2;" : "=r"(d) : "f"(hi), "f"(lo));
    return d;
}
__device__ __forceinline__ float lo16f(uint32_t p) { return __uint_as_float(p << 16); }
__device__ __forceinline__ float hi16f(uint32_t p) { return __uint_as_float(p & 0xFFFF0000u); }

// Volatile shared accesses: anti-hoist for IN-LOOP data (prevents unbounded
// weight->register promotion across the batch loop).
__device__ __forceinline__ uint4 lds128u(uint32_t a) {
    uint4 v;
    asm volatile("ld.shared.v4.b32 {%0,%1,%2,%3}, [%4];"
                 : "=r"(v.x), "=r"(v.y), "=r"(v.z), "=r"(v.w) : "r"(a));
    return v;
}
__device__ __forceinline__ float2 ldsf2v(uint32_t a) {
    float2 v;
    asm volatile("ld.shared.v2.f32 {%0, %1}, [%2];" : "=f"(v.x), "=f"(v.y) : "r"(a));
    return v;
}
__device__ __forceinline__ float4 ldsf4v(uint32_t a) {
    float4 v;
    asm volatile("ld.shared.v4.f32 {%0, %1, %2, %3}, [%4];"
                 : "=f"(v.x), "=f"(v.y), "=f"(v.z), "=f"(v.w) : "r"(a));
    return v;
}
__device__ __forceinline__ void sts128u(uint32_t a, uint32_t v0, uint32_t v1,
                                        uint32_t v2, uint32_t v3) {
    asm volatile("st.shared.v4.b32 [%0], {%1,%2,%3,%4};"
                 :: "r"(a), "r"(v0), "r"(v1), "r"(v2), "r"(v3));
}

// Tensor-core MMA, bf16 m16n8k16 (plain sm_80+ PTX; not 'a'-gated).
__device__ __forceinline__ void mma_bf16(float* d, const uint32_t* a,
                                         uint32_t b0, uint32_t b1) {
    asm volatile(
        "mma.sync.aligned.m16n8k16.row.col.f32.bf16.bf16.f32 "
        "{%0,%1,%2,%3}, {%4,%5,%6,%7}, {%8,%9}, {%0,%1,%2,%3};"
        : "+f"(d[0]), "+f"(d[1]), "+f"(d[2]), "+f"(d[3])
        : "r"(a[0]), "r"(a[1]), "r"(a[2]), "r"(a[3]), "r"(b0), "r"(b1));
}

// One 3x-bf16-split [32x32x32] warp GEMM. aBase = this warp's A block in
// SMEM; bf = register-resident B fragments [kt*4+nt] = (bh0,bh1,bl0,bl1).
__device__ __forceinline__ void wgemm(uint32_t aBase, const uint4* bf,
                                      int lane, float* d) {
    const int g = lane >> 2, t = lane & 3;
    #pragma unroll
    for (int mt = 0; mt < 2; mt++) {
        const uint32_t r0 = aBase + (mt * 16 + g) * ROWSTR + t * 32;
        const uint32_t r1 = aBase + (mt * 16 + g + 8) * ROWSTR + t * 32;
        const uint4 A0k0 = lds128u(r0);        // a0hi, a0lo, a2hi, a2lo (kt=0)
        const uint4 A1k0 = lds128u(r1);        // a1hi, a1lo, a3hi, a3lo (kt=0)
        const uint4 A0k1 = lds128u(r0 + 16);   // kt=1
        const uint4 A1k1 = lds128u(r1 + 16);
        const uint32_t ah0[4] = {A0k0.x, A1k0.x, A0k0.z, A1k0.z};
        const uint32_t al0[4] = {A0k0.y, A1k0.y, A0k0.w, A1k0.w};
        const uint32_t ah1[4] = {A0k1.x, A1k1.x, A0k1.z, A1k1.z};
        const uint32_t al1[4] = {A0k1.y, A1k1.y, A0k1.w, A1k1.w};
        #pragma unroll
        for (int kt = 0; kt < 2; kt++) {
            const uint32_t* ah = kt ? ah1 : ah0;
            const uint32_t* al = kt ? al1 : al0;
            #pragma unroll
            for (int nt = 0; nt < 4; nt++) {
                const uint4 bv = bf[kt * 4 + nt];
                float* dd = d + (mt * 4 + nt) * 4;
                mma_bf16(dd, ah, bv.x, bv.y);   // hi*hi
                mma_bf16(dd, al, bv.x, bv.y);   // lo*hi
                mma_bf16(dd, ah, bv.z, bv.w);   // hi*lo
            }
        }
    }
}

__global__ __launch_bounds__(128, 3) void g_tensor3d_mma(
    const float* __restrict__ z,
    const float* __restrict__ data,
    const float* __restrict__ z_data,
    const float* __restrict__ lerp,
    const int*   __restrict__ x0,
    const int*   __restrict__ y0,
    const int*   __restrict__ x1,
    const int*   __restrict__ y1,
    const float* __restrict__ W1,
    const float* __restrict__ b1,
    const float* __restrict__ W2,
    const float* __restrict__ b2,
    const float* __restrict__ W3,
    const float* __restrict__ b3,
    float*       __restrict__ out)
{
    extern __shared__ float smem[];
    const uint32_t sb = sptr(smem);
    const int tid = threadIdx.x;
    const int lane = tid & 31;
    const int warp = tid >> 5;
    const int g = lane >> 2, t = lane & 3;

    // ---- Init: B fragment table (hi/lo combined 16B entries, lane-major) ----
    #pragma unroll
    for (int it = 0; it < 4; it++) {
        const int s = it * 128 + tid;       // 0..511
        const int ln = s & 31;
        const int e = s >> 5;               // 0..15
        const int nt = e & 3, kt = (e >> 2) & 1, layer = (e >> 3) & 1;
        const int lg = ln >> 2, lt = ln & 3;
        const int k0 = 16 * kt + 2 * lt;
        const int n  = 8 * nt + lg;
        const float* W = layer ? W2 : W1;
        const float wa = W[k0 * 32 + n];
        const float wb = W[(k0 + 1) * 32 + n];
        const float wc = W[(k0 + 8) * 32 + n];
        const float wd = W[(k0 + 9) * 32 + n];
        const uint32_t bh0 = pkbf2(wa, wb);
        const uint32_t bh1 = pkbf2(wc, wd);
        const uint32_t bl0 = pkbf2(wa - lo16f(bh0), wb - hi16f(bh0));
        const uint32_t bl1 = pkbf2(wc - lo16f(bh1), wd - hi16f(bh1));
        uint4 v; v.x = bh0; v.y = bh1; v.z = bl0; v.w = bl1;
        *(uint4*)((char*)smem + OFF_B + s * 16) = v;
    }
    // z features zf[8][32].
    #pragma unroll
    for (int k = 0; k < 2; k++) {
        const int tt = tid + 128 * k;
        const int b = tt >> 5, i = tt & 31;
        const float zn = 63.0f * z[b];
        int z0i = (int)zn;
        if (z0i < 0) z0i = 0;
        if (z0i > 63) z0i = 63;
        int z1i = z0i + 1;
        if (z1i > 63) z1i = 63;
        const float zl = zn - truncf(zn);
        *(float*)((char*)smem + OFF_ZF + (b * 32 + i) * 4) =
            z_data[z0i * 32 + i] * (1.0f - zl) + z_data[z1i * 32 + i] * zl;
    }
    if (tid < 32) {
        *(float*)((char*)smem + OFF_B1 + tid * 4) = b1[tid];
        *(float*)((char*)smem + OFF_B2 + tid * 4) = b2[tid];
        *(float*)((char*)smem + OFF_W3 + tid * 4) = W3[tid];
    }
    if (tid == 0) *(float*)((char*)smem + OFF_B3) = b3[0];

    // ---- Bilinear gather -> xy[32] registers ----
    const int pixbase = blockIdx.x * 128;
    const int p = pixbase + tid;
    const float wx = lerp[2 * p + 0];
    const float wy = lerp[2 * p + 1];
    const int ix0 = x0[p], iy0 = y0[p], ix1 = x1[p], iy1 = y1[p];
    const float4* p00 = (const float4*)(data + (iy0 * 512 + ix0) * 32);
    const float4* p10 = (const float4*)(data + (iy0 * 512 + ix1) * 32);
    const float4* p01 = (const float4*)(data + (iy1 * 512 + ix0) * 32);
    const float4* p11 = (const float4*)(data + (iy1 * 512 + ix1) * 32);
    const float w00 = (1.0f - wx) * (1.0f - wy);
    const float w10 = wx * (1.0f - wy);
    const float w01 = (1.0f - wx) * wy;
    const float w11 = wx * wy;
    float xy[32];
    #pragma unroll
    for (int q = 0; q < 8; q++) {
        const float4 a = p00[q];
        const float4 c = p10[q];
        const float4 e = p01[q];
        const float4 gg = p11[q];
        xy[4 * q + 0] = a.x * w00 + c.x * w10 + e.x * w01 + gg.x * w11;
        xy[4 * q + 1] = a.y * w00 + c.y * w10 + e.y * w01 + gg.y * w11;
        xy[4 * q + 2] = a.z * w00 + c.z * w10 + e.z * w01 + gg.z * w11;
        xy[4 * q + 3] = a.w * w00 + c.w * w10 + e.w * w01 + gg.w * w11;
    }
    __syncthreads();   // tables ready

    // ---- Consume B table into registers (once; bounded 64 regs) ----
    uint4 bR1[8], bR2[8];
    #pragma unroll
    for (int e = 0; e < 8; e++) {
        bR1[e] = *(const uint4*)((char*)smem + OFF_B + (e * 32 + lane) * 16);
        bR2[e] = *(const uint4*)((char*)smem + OFF_B + 4096 + (e * 32 + lane) * 16);
    }

    const float b3v = *(const float*)((char*)smem + OFF_B3);
    const uint32_t aX  = sb + OFF_A + warp * 9216;
    const uint32_t aH  = aX + 4608;
    const uint32_t myX = aX + lane * ROWSTR;   // this thread's X row

    #pragma unroll 1
    for (int b = 0; b < 8; b++) {
        // ---- Build X_b = xy .* zf_b, bf16 hi/lo interleaved layout ----
        __syncwarp();   // WAR vs previous gemm1 reads
        {
            float zf[32];
            #pragma unroll
            for (int q = 0; q < 8; q++) {
                const float4 v = ldsf4v(sb + OFF_ZF + b * 128 + q * 16);
                zf[4 * q + 0] = v.x; zf[4 * q + 1] = v.y;
                zf[4 * q + 2] = v.z; zf[4 * q + 3] = v.w;
            }
            #pragma unroll
            for (int c = 0; c < 4; c++) {
                uint32_t hw[4], lw[4];
                #pragma unroll
                for (int j = 0; j < 4; j++) {
                    const int col = 2 * c + 8 * j;
                    const float v0 = xy[col] * zf[col];
                    const float v1 = xy[col + 1] * zf[col + 1];
                    const uint32_t hp = pkbf2(v0, v1);
                    hw[j] = hp;
                    lw[j] = pkbf2(v0 - lo16f(hp), v1 - hi16f(hp));
                }
                sts128u(myX + c * 32,      hw[0], lw[0], hw[1], lw[1]);
                sts128u(myX + c * 32 + 16, hw[2], lw[2], hw[3], lw[3]);
            }
        }
        __syncwarp();

        // ---- Layer 1 GEMM ----
        float d1[32];
        #pragma unroll
        for (int m = 0; m < 32; m++) d1[m] = 0.0f;
        wgemm(aX, bR1, lane, d1);

        // ---- Epilogue 1: H = relu(d1 + b1), hi/lo split, 2x sts128 per row ----
        __syncwarp();   // WAR vs previous gemm2 reads
        {
            float2 bb[4];
            #pragma unroll
            for (int nt = 0; nt < 4; nt++)
                bb[nt] = ldsf2v(sb + OFF_B1 + (nt * 8 + 2 * t) * 4);
            #pragma unroll
            for (int mt = 0; mt < 2; mt++) {
                uint32_t wr0[8], wr1[8];
                #pragma unroll
                for (int nt = 0; nt < 4; nt++) {
                    const float* dd = d1 + (mt * 4 + nt) * 4;
                    float v0 = fmaxf(dd[0] + bb[nt].x, 0.0f);
                    float v1 = fmaxf(dd[1] + bb[nt].y, 0.0f);
                    uint32_t hp = pkbf2(v0, v1);
                    wr0[nt * 2 + 0] = hp;
                    wr0[nt * 2 + 1] = pkbf2(v0 - lo16f(hp), v1 - hi16f(hp));
                    v0 = fmaxf(dd[2] + bb[nt].x, 0.0f);
                    v1 = fmaxf(dd[3] + bb[nt].y, 0.0f);
                    hp = pkbf2(v0, v1);
                    wr1[nt * 2 + 0] = hp;
                    wr1[nt * 2 + 1] = pkbf2(v0 - lo16f(hp), v1 - hi16f(hp));
                }
                const uint32_t r0a = aH + (mt * 16 + g) * ROWSTR + t * 32;
                const uint32_t r1a = aH + (mt * 16 + g + 8) * ROWSTR + t * 32;
                sts128u(r0a,      wr0[0], wr0[1], wr0[2], wr0[3]);
                sts128u(r0a + 16, wr0[4], wr0[5], wr0[6], wr0[7]);
                sts128u(r1a,      wr1[0], wr1[1], wr1[2], wr1[3]);
                sts128u(r1a + 16, wr1[4], wr1[5], wr1[6], wr1[7]);
            }
        }
        __syncwarp();

        // ---- Layer 2 GEMM ----
        float d2[32];
        #pragma unroll
        for (int m = 0; m < 32; m++) d2[m] = 0.0f;
        wgemm(aH, bR2, lane, d2);

        // ---- Epilogue 2: relu(d2 + b2) . W3, cross-lane reduce, store ----
        float pr[4] = {0.0f, 0.0f, 0.0f, 0.0f};
        #pragma unroll
        for (int nt = 0; nt < 4; nt++) {
            const float2 bp = ldsf2v(sb + OFF_B2 + (nt * 8 + 2 * t) * 4);
            const float2 wp = ldsf2v(sb + OFF_W3 + (nt * 8 + 2 * t) * 4);
            #pragma unroll
            for (int mt = 0; mt < 2; mt++) {
                const float* dd = d2 + (mt * 4 + nt) * 4;
                pr[mt * 2 + 0] = fmaf(fmaxf(dd[0] + bp.x, 0.0f), wp.x,
                                 fmaf(fmaxf(dd[1] + bp.y, 0.0f), wp.y, pr[mt * 2 + 0]));
                pr[mt * 2 + 1] = fmaf(fmaxf(dd[2] + bp.x, 0.0f), wp.x,
                                 fmaf(fmaxf(dd[3] + bp.y, 0.0f), wp.y, pr[mt * 2 + 1]));
            }
        }
        #pragma unroll
        for (int m = 0; m < 4; m++) {
            pr[m] += __shfl_xor_sync(0xFFFFFFFFu, pr[m], 1);
            pr[m] += __shfl_xor_sync(0xFFFFFFFFu, pr[m], 2);
        }
        if (t == 0) {
            float* ob = out + b * NPIX + pixbase + warp * 32;
            ob[g]          = pr[0] + b3v;
            ob[g + 8]      = pr[1] + b3v;
            ob[16 + g]     = pr[2] + b3v;
            ob[16 + g + 8] = pr[3] + b3v;
        }
    }
}

extern "C" void kernel_launch(void* const* d_in, const int* in_sizes, int n_in,
                              void* d_out, int out_size) {
    const float* z      = (const float*)d_in[0];
    const float* data   = (const float*)d_in[1];
    const float* z_data = (const float*)d_in[2];
    const float* lerp   = (const float*)d_in[3];
    const int*   x0     = (const int*)d_in[4];
    const int*   y0     = (const int*)d_in[5];
    const int*   x1     = (const int*)d_in[6];
    const int*   y1     = (const int*)d_in[7];
    const float* W1     = (const float*)d_in[8];
    const float* b1     = (const float*)d_in[9];
    const float* W2     = (const float*)d_in[10];
    const float* b2     = (const float*)d_in[11];
    const float* W3     = (const float*)d_in[12];
    const float* b3     = (const float*)d_in[13];
    float* out = (float*)d_out;

    cudaFuncSetAttribute(g_tensor3d_mma,
                         cudaFuncAttributeMaxDynamicSharedMemorySize, SMEM_BYTES);

    g_tensor3d_mma<<<NPIX / 128, 128, SMEM_BYTES>>>(z, data, z_data, lerp,
                                                    x0, y0, x1, y1,
                                                    W1, b1, W2, b2, W3, b3, out);
}

// round 15
// speedup vs baseline: 2.1481x; 1.2179x over previous
#include <cuda_runtime.h>
#include <cstdint>

#define NPIX (512*512)

// SMEM byte offsets.
#define OFF_B1T 0       // per-batch B1 frag tables: 8 x 4096B (zf folded in)
#define OFF_B2T 32768   // B2 frag table: 4096B
#define OFF_AST 36864   // per-warp X staging (init only): 4 x 4608B
#define OFF_ZF  55296   // zf[8][32] f32 (init only)
#define OFF_BB1 56320
#define OFF_BB2 56448
#define OFF_W3  56576
#define OFF_B3  56704
#define SMEM_BYTES 56832

#define ROWSTR 144

__device__ __forceinline__ uint32_t sptr(const void* p) {
    return (uint32_t)__cvta_generic_to_shared(p);
}
// pack (lo, hi) floats -> bf16x2 (lo in low half)
__device__ __forceinline__ uint32_t pkbf2(float lo, float hi) {
    uint32_t d;
    asm("cvt.rn.bf16x2.f32 %0, %1, %2;" : "=r"(d) : "f"(hi), "f"(lo));
    return d;
}
__device__ __forceinline__ float lo16f(uint32_t p) { return __uint_as_float(p << 16); }
__device__ __forceinline__ float hi16f(uint32_t p) { return __uint_as_float(p & 0xFFFF0000u); }

// Volatile shared loads for IN-LOOP data (anti-hoist: keeps the per-batch B1
// fragments out of the register file except at their use site).
__device__ __forceinline__ uint4 lds128u(uint32_t a) {
    uint4 v;
    asm volatile("ld.shared.v4.b32 {%0,%1,%2,%3}, [%4];"
                 : "=r"(v.x), "=r"(v.y), "=r"(v.z), "=r"(v.w) : "r"(a));
    return v;
}
__device__ __forceinline__ void sts128u(uint32_t a, uint32_t v0, uint32_t v1,
                                        uint32_t v2, uint32_t v3) {
    asm volatile("st.shared.v4.b32 [%0], {%1,%2,%3,%4};"
                 :: "r"(a), "r"(v0), "r"(v1), "r"(v2), "r"(v3));
}

// Tensor-core MMA, bf16 m16n8k16 (plain sm_80+ PTX).
__device__ __forceinline__ void mma_bf16(float* d, const uint32_t* a,
                                         uint32_t b0, uint32_t b1) {
    asm volatile(
        "mma.sync.aligned.m16n8k16.row.col.f32.bf16.bf16.f32 "
        "{%0,%1,%2,%3}, {%4,%5,%6,%7}, {%8,%9}, {%0,%1,%2,%3};"
        : "+f"(d[0]), "+f"(d[1]), "+f"(d[2]), "+f"(d[3])
        : "r"(a[0]), "r"(a[1]), "r"(a[2]), "r"(a[3]), "r"(b0), "r"(b1));
}

__global__ __launch_bounds__(128, 3) void g_tensor3d_mma(
    const float* __restrict__ z,
    const float* __restrict__ data,
    const float* __restrict__ z_data,
    const float* __restrict__ lerp,
    const int*   __restrict__ x0,
    const int*   __restrict__ y0,
    const int*   __restrict__ x1,
    const int*   __restrict__ y1,
    const float* __restrict__ W1,
    const float* __restrict__ b1,
    const float* __restrict__ W2,
    const float* __restrict__ b2,
    const float* __restrict__ W3,
    const float* __restrict__ b3,
    float*       __restrict__ out)
{
    extern __shared__ float smem[];
    const uint32_t sb = sptr(smem);
    const int tid = threadIdx.x;
    const int lane = tid & 31;
    const int warp = tid >> 5;
    const int g = lane >> 2, t = lane & 3;

    // ---- Stage 1: z features into SMEM ----
    #pragma unroll
    for (int k = 0; k < 2; k++) {
        const int tt = tid + 128 * k;
        const int b = tt >> 5, i = tt & 31;
        const float zn = 63.0f * z[b];
        int z0i = (int)zn;
        if (z0i < 0) z0i = 0;
        if (z0i > 63) z0i = 63;
        int z1i = z0i + 1;
        if (z1i > 63) z1i = 63;
        const float zl = zn - truncf(zn);
        *(float*)((char*)smem + OFF_ZF + (b * 32 + i) * 4) =
            z_data[z0i * 32 + i] * (1.0f - zl) + z_data[z1i * 32 + i] * zl;
    }
    if (tid < 32) {
        *(float*)((char*)smem + OFF_BB1 + tid * 4) = b1[tid];
        *(float*)((char*)smem + OFF_BB2 + tid * 4) = b2[tid];
        *(float*)((char*)smem + OFF_W3 + tid * 4) = W3[tid];
    }
    if (tid == 0) *(float*)((char*)smem + OFF_B3) = b3[0];
    __syncthreads();   // zf ready

    // ---- Stage 2: build fragment tables ----
    // B1 per-batch (zf folded in): 8 batches x 8 (kt,nt) x 32 lanes x 16B.
    #pragma unroll
    for (int it = 0; it < 16; it++) {
        const int s = it * 128 + tid;          // 0..2047
        const int ln = s & 31;
        const int e5 = s >> 5;                 // 0..63
        const int e = e5 & 7, b = e5 >> 3;
        const int nt = e & 3, kt = e >> 2;
        const int lg = ln >> 2, lt = ln & 3;
        const int k0 = 16 * kt + 2 * lt;
        const int n  = 8 * nt + lg;
        const float* zfb = (const float*)((char*)smem + OFF_ZF + b * 128);
        const float wa = zfb[k0]     * W1[k0 * 32 + n];
        const float wb = zfb[k0 + 1] * W1[(k0 + 1) * 32 + n];
        const float wc = zfb[k0 + 8] * W1[(k0 + 8) * 32 + n];
        const float wd = zfb[k0 + 9] * W1[(k0 + 9) * 32 + n];
        const uint32_t bh0 = pkbf2(wa, wb);
        const uint32_t bh1 = pkbf2(wc, wd);
        const uint32_t bl0 = pkbf2(wa - lo16f(bh0), wb - hi16f(bh0));
        const uint32_t bl1 = pkbf2(wc - lo16f(bh1), wd - hi16f(bh1));
        uint4 v; v.x = bh0; v.y = bh1; v.z = bl0; v.w = bl1;
        *(uint4*)((char*)smem + OFF_B1T + b * 4096 + ((kt * 4 + nt) * 32 + ln) * 16) = v;
    }
    // B2 table (batch-invariant).
    #pragma unroll
    for (int it = 0; it < 2; it++) {
        const int s = it * 128 + tid;          // 0..255
        const int ln = s & 31;
        const int e = s >> 5;                  // 0..7
        const int nt = e & 3, kt = e >> 2;
        const int lg = ln >> 2, lt = ln & 3;
        const int k0 = 16 * kt + 2 * lt;
        const int n  = 8 * nt + lg;
        const float wa = W2[k0 * 32 + n];
        const float wb = W2[(k0 + 1) * 32 + n];
        const float wc = W2[(k0 + 8) * 32 + n];
        const float wd = W2[(k0 + 9) * 32 + n];
        const uint32_t bh0 = pkbf2(wa, wb);
        const uint32_t bh1 = pkbf2(wc, wd);
        const uint32_t bl0 = pkbf2(wa - lo16f(bh0), wb - hi16f(bh0));
        const uint32_t bl1 = pkbf2(wc - lo16f(bh1), wd - hi16f(bh1));
        uint4 v; v.x = bh0; v.y = bh1; v.z = bl0; v.w = bl1;
        *(uint4*)((char*)smem + OFF_B2T + ((kt * 4 + nt) * 32 + ln) * 16) = v;
    }

    // ---- Bilinear gather -> xy[32], pack into per-warp A staging ----
    const int pixbase = blockIdx.x * 128;
    const int p = pixbase + tid;
    const float wx = lerp[2 * p + 0];
    const float wy = lerp[2 * p + 1];
    const int ix0 = x0[p], iy0 = y0[p], ix1 = x1[p], iy1 = y1[p];
    const float4* p00 = (const float4*)(data + (iy0 * 512 + ix0) * 32);
    const float4* p10 = (const float4*)(data + (iy0 * 512 + ix1) * 32);
    const float4* p01 = (const float4*)(data + (iy1 * 512 + ix0) * 32);
    const float4* p11 = (const float4*)(data + (iy1 * 512 + ix1) * 32);
    const float w00 = (1.0f - wx) * (1.0f - wy);
    const float w10 = wx * (1.0f - wy);
    const float w01 = (1.0f - wx) * wy;
    const float w11 = wx * wy;
    float xy[32];
    #pragma unroll
    for (int q = 0; q < 8; q++) {
        const float4 a = p00[q];
        const float4 c = p10[q];
        const float4 e = p01[q];
        const float4 gg = p11[q];
        xy[4 * q + 0] = a.x * w00 + c.x * w10 + e.x * w01 + gg.x * w11;
        xy[4 * q + 1] = a.y * w00 + c.y * w10 + e.y * w01 + gg.y * w11;
        xy[4 * q + 2] = a.z * w00 + c.z * w10 + e.z * w01 + gg.z * w11;
        xy[4 * q + 3] = a.w * w00 + c.w * w10 + e.w * w01 + gg.w * w11;
    }
    const uint32_t aX  = sb + OFF_AST + warp * 4608;
    const uint32_t myX = aX + lane * ROWSTR;
    #pragma unroll
    for (int c = 0; c < 4; c++) {
        uint32_t hw[4], lw[4];
        #pragma unroll
        for (int j = 0; j < 4; j++) {
            const int col = 2 * c + 8 * j;
            const float v0 = xy[col];
            const float v1 = xy[col + 1];
            const uint32_t hp = pkbf2(v0, v1);
            hw[j] = hp;
            lw[j] = pkbf2(v0 - lo16f(hp), v1 - hi16f(hp));
        }
        sts128u(myX + c * 32,      hw[0], lw[0], hw[1], lw[1]);
        sts128u(myX + c * 32 + 16, hw[2], lw[2], hw[3], lw[3]);
    }
    __syncthreads();   // tables + staging ready

    // ---- Load batch-invariant register state ----
    // X fragments (A operand of GEMM1, reused by all 8 batches).
    uint32_t xh[2][2][4], xl[2][2][4];
    #pragma unroll
    for (int mt = 0; mt < 2; mt++) {
        const uint32_t r0 = aX + (mt * 16 + g) * ROWSTR + t * 32;
        const uint32_t r1 = aX + (mt * 16 + g + 8) * ROWSTR + t * 32;
        const uint4 A0k0 = lds128u(r0);
        const uint4 A1k0 = lds128u(r1);
        const uint4 A0k1 = lds128u(r0 + 16);
        const uint4 A1k1 = lds128u(r1 + 16);
        xh[mt][0][0] = A0k0.x; xh[mt][0][1] = A1k0.x; xh[mt][0][2] = A0k0.z; xh[mt][0][3] = A1k0.z;
        xl[mt][0][0] = A0k0.y; xl[mt][0][1] = A1k0.y; xl[mt][0][2] = A0k0.w; xl[mt][0][3] = A1k0.w;
        xh[mt][1][0] = A0k1.x; xh[mt][1][1] = A1k1.x; xh[mt][1][2] = A0k1.z; xh[mt][1][3] = A1k1.z;
        xl[mt][1][0] = A0k1.y; xl[mt][1][1] = A1k1.y; xl[mt][1][2] = A0k1.w; xl[mt][1][3] = A1k1.w;
    }
    // B2 fragments (bounded 32 regs).
    uint4 bR2[8];
    #pragma unroll
    for (int e = 0; e < 8; e++)
        bR2[e] = *(const uint4*)((char*)smem + OFF_B2T + (e * 32 + lane) * 16);
    // Bias fragments.
    float2 bb1[4], bb2[4], ww3[4];
    #pragma unroll
    for (int nt = 0; nt < 4; nt++) {
        bb1[nt] = *(const float2*)((char*)smem + OFF_BB1 + (nt * 8 + 2 * t) * 4);
        bb2[nt] = *(const float2*)((char*)smem + OFF_BB2 + (nt * 8 + 2 * t) * 4);
        ww3[nt] = *(const float2*)((char*)smem + OFF_W3 + (nt * 8 + 2 * t) * 4);
    }
    const float b3v = *(const float*)((char*)smem + OFF_B3);

    #pragma unroll 1
    for (int b = 0; b < 8; b++) {
        const uint32_t bT1 = sb + OFF_B1T + b * 4096;

        // ---- GEMM1: D1 = X @ B1_b (A in regs, B volatile per batch) ----
        float d1[2][4][4];
        #pragma unroll
        for (int mt = 0; mt < 2; mt++)
            #pragma unroll
            for (int nt = 0; nt < 4; nt++)
                #pragma unroll
                for (int m = 0; m < 4; m++) d1[mt][nt][m] = 0.0f;

        #pragma unroll
        for (int kt = 0; kt < 2; kt++) {
            #pragma unroll
            for (int nt = 0; nt < 4; nt++) {
                const uint4 bv = lds128u(bT1 + ((kt * 4 + nt) * 32 + lane) * 16);
                #pragma unroll
                for (int mt = 0; mt < 2; mt++) {
                    mma_bf16(d1[mt][nt], xh[mt][kt], bv.x, bv.y);
                    mma_bf16(d1[mt][nt], xl[mt][kt], bv.x, bv.y);
                    mma_bf16(d1[mt][nt], xh[mt][kt], bv.z, bv.w);
                }
            }
        }

        // ---- Epilogue 1 (registers only): relu(d1+b1) -> A fragments of GEMM2
        // C-frag (rows g,g+8; cols nt*8+2t,+1) == A-frag (kt=nt>>1, a0/a2 sel by nt&1).
        uint32_t ah[2][2][4], al[2][2][4];
        #pragma unroll
        for (int mt = 0; mt < 2; mt++) {
            #pragma unroll
            for (int nt = 0; nt < 4; nt++) {
                const float* c = d1[mt][nt];
                const int kt = nt >> 1;
                const int ix = (nt & 1) * 2;
                float v0 = fmaxf(c[0] + bb1[nt].x, 0.0f);
                float v1 = fmaxf(c[1] + bb1[nt].y, 0.0f);
                uint32_t hp = pkbf2(v0, v1);
                ah[mt][kt][ix] = hp;
                al[mt][kt][ix] = pkbf2(v0 - lo16f(hp), v1 - hi16f(hp));
                v0 = fmaxf(c[2] + bb1[nt].x, 0.0f);
                v1 = fmaxf(c[3] + bb1[nt].y, 0.0f);
                hp = pkbf2(v0, v1);
                ah[mt][kt][ix + 1] = hp;
                al[mt][kt][ix + 1] = pkbf2(v0 - lo16f(hp), v1 - hi16f(hp));
            }
        }

        // ---- GEMM2: D2 = H @ B2 (all-register operands) ----
        float d2[2][4][4];
        #pragma unroll
        for (int mt = 0; mt < 2; mt++)
            #pragma unroll
            for (int nt = 0; nt < 4; nt++)
                #pragma unroll
                for (int m = 0; m < 4; m++) d2[mt][nt][m] = 0.0f;

        #pragma unroll
        for (int kt = 0; kt < 2; kt++) {
            #pragma unroll
            for (int nt = 0; nt < 4; nt++) {
                const uint4 bv = bR2[kt * 4 + nt];
                #pragma unroll
                for (int mt = 0; mt < 2; mt++) {
                    mma_bf16(d2[mt][nt], ah[mt][kt], bv.x, bv.y);
                    mma_bf16(d2[mt][nt], al[mt][kt], bv.x, bv.y);
                    mma_bf16(d2[mt][nt], ah[mt][kt], bv.z, bv.w);
                }
            }
        }

        // ---- Epilogue 2: relu(d2+b2).W3, cross-lane reduce, store ----
        float pr[4] = {0.0f, 0.0f, 0.0f, 0.0f};
        #pragma unroll
        for (int nt = 0; nt < 4; nt++) {
            #pragma unroll
            for (int mt = 0; mt < 2; mt++) {
                const float* dd = d2[mt][nt];
                pr[mt * 2 + 0] = fmaf(fmaxf(dd[0] + bb2[nt].x, 0.0f), ww3[nt].x,
                                 fmaf(fmaxf(dd[1] + bb2[nt].y, 0.0f), ww3[nt].y, pr[mt * 2 + 0]));
                pr[mt * 2 + 1] = fmaf(fmaxf(dd[2] + bb2[nt].x, 0.0f), ww3[nt].x,
                                 fmaf(fmaxf(dd[3] + bb2[nt].y, 0.0f), ww3[nt].y, pr[mt * 2 + 1]));
            }
        }
        #pragma unroll
        for (int m = 0; m < 4; m++) {
            pr[m] += __shfl_xor_sync(0xFFFFFFFFu, pr[m], 1);
            pr[m] += __shfl_xor_sync(0xFFFFFFFFu, pr[m], 2);
        }
        if (t == 0) {
            float* ob = out + b * NPIX + pixbase + warp * 32;
            ob[g]          = pr[0] + b3v;
            ob[g + 8]      = pr[1] + b3v;
            ob[16 + g]     = pr[2] + b3v;
            ob[16 + g + 8] = pr[3] + b3v;
        }
    }
}

extern "C" void kernel_launch(void* const* d_in, const int* in_sizes, int n_in,
                              void* d_out, int out_size) {
    const float* z      = (const float*)d_in[0];
    const float* data   = (const float*)d_in[1];
    const float* z_data = (const float*)d_in[2];
    const float* lerp   = (const float*)d_in[3];
    const int*   x0     = (const int*)d_in[4];
    const int*   y0     = (const int*)d_in[5];
    const int*   x1     = (const int*)d_in[6];
    const int*   y1     = (const int*)d_in[7];
    const float* W1     = (const float*)d_in[8];
    const float* b1     = (const float*)d_in[9];
    const float* W2     = (const float*)d_in[10];
    const float* b2     = (const float*)d_in[11];
    const float* W3     = (const float*)d_in[12];
    const float* b3     = (const float*)d_in[13];
    float* out = (float*)d_out;

    cudaFuncSetAttribute(g_tensor3d_mma,
                         cudaFuncAttributeMaxDynamicSharedMemorySize, SMEM_BYTES);

    g_tensor3d_mma<<<NPIX / 128, 128, SMEM_BYTES>>>(z, data, z_data, lerp,
                                                    x0, y0, x1, y1,
                                                    W1, b1, W2, b2, W3, b3, out);
}

// round 16
// speedup vs baseline: 2.5625x; 1.1930x over previous
#include <cuda_runtime.h>
#include <cstdint>

#define NPIX (512*512)

// SMEM byte offsets.
#define OFF_B1T 0       // per-batch B1 frag tables (fp16, zf folded): 8 x 2048B
#define OFF_B2T 16384   // B2 frag table: 2048B
#define OFF_AST 18432   // per-warp X staging (init only): 4 x 4608B
#define OFF_ZF  36864   // zf[8][32] f32 (init only)
#define OFF_BB1 37888
#define OFF_BB2 38016
#define OFF_W3  38144
#define OFF_B3  38272
#define SMEM_BYTES 38400

#define ROWSTR 144
#define SX 4096.0f      // X scale (keeps X_lo out of fp16 denormals)
#define SH 1024.0f      // H scale

__device__ __forceinline__ uint32_t sptr(const void* p) {
    return (uint32_t)__cvta_generic_to_shared(p);
}
// pack (lo, hi) floats -> fp16x2 (first arg in low half)
__device__ __forceinline__ uint32_t pkhf2(float lo, float hi) {
    uint32_t d;
    asm("cvt.rn.f16x2.f32 %0, %1, %2;" : "=r"(d) : "f"(hi), "f"(lo));
    return d;
}
__device__ __forceinline__ float lo16h(uint32_t p) {
    float f;
    asm("{.reg .b16 a, b;\n\t mov.b32 {a, b}, %1;\n\t cvt.f32.f16 %0, a;}"
        : "=f"(f) : "r"(p));
    return f;
}
__device__ __forceinline__ float hi16h(uint32_t p) {
    float f;
    asm("{.reg .b16 a, b;\n\t mov.b32 {a, b}, %1;\n\t cvt.f32.f16 %0, b;}"
        : "=f"(f) : "r"(p));
    return f;
}

// Volatile shared loads for IN-LOOP data (anti-hoist).
__device__ __forceinline__ uint4 lds128u(uint32_t a) {
    uint4 v;
    asm volatile("ld.shared.v4.b32 {%0,%1,%2,%3}, [%4];"
                 : "=r"(v.x), "=r"(v.y), "=r"(v.z), "=r"(v.w) : "r"(a));
    return v;
}
__device__ __forceinline__ uint2 lds64u(uint32_t a) {
    uint2 v;
    asm volatile("ld.shared.v2.b32 {%0, %1}, [%2];" : "=r"(v.x), "=r"(v.y) : "r"(a));
    return v;
}
__device__ __forceinline__ void sts128u(uint32_t a, uint32_t v0, uint32_t v1,
                                        uint32_t v2, uint32_t v3) {
    asm volatile("st.shared.v4.b32 [%0], {%1,%2,%3,%4};"
                 :: "r"(a), "r"(v0), "r"(v1), "r"(v2), "r"(v3));
}

// Tensor-core MMA, fp16 m16n8k16 with fp32 accum (plain sm_80+ PTX).
__device__ __forceinline__ void mma_f16(float* d, const uint32_t* a,
                                        uint32_t b0, uint32_t b1) {
    asm volatile(
        "mma.sync.aligned.m16n8k16.row.col.f32.f16.f16.f32 "
        "{%0,%1,%2,%3}, {%4,%5,%6,%7}, {%8,%9}, {%0,%1,%2,%3};"
        : "+f"(d[0]), "+f"(d[1]), "+f"(d[2]), "+f"(d[3])
        : "r"(a[0]), "r"(a[1]), "r"(a[2]), "r"(a[3]), "r"(b0), "r"(b1));
}

__global__ __launch_bounds__(128, 3) void g_tensor3d_mma(
    const float* __restrict__ z,
    const float* __restrict__ data,
    const float* __restrict__ z_data,
    const float* __restrict__ lerp,
    const int*   __restrict__ x0,
    const int*   __restrict__ y0,
    const int*   __restrict__ x1,
    const int*   __restrict__ y1,
    const float* __restrict__ W1,
    const float* __restrict__ b1,
    const float* __restrict__ W2,
    const float* __restrict__ b2,
    const float* __restrict__ W3,
    const float* __restrict__ b3,
    float*       __restrict__ out)
{
    extern __shared__ float smem[];
    const uint32_t sb = sptr(smem);
    const int tid = threadIdx.x;
    const int lane = tid & 31;
    const int warp = tid >> 5;
    const int g = lane >> 2, t = lane & 3;

    // ---- Stage 1: z features into SMEM ----
    #pragma unroll
    for (int k = 0; k < 2; k++) {
        const int tt = tid + 128 * k;
        const int b = tt >> 5, i = tt & 31;
        const float zn = 63.0f * z[b];
        int z0i = (int)zn;
        if (z0i < 0) z0i = 0;
        if (z0i > 63) z0i = 63;
        int z1i = z0i + 1;
        if (z1i > 63) z1i = 63;
        const float zl = zn - truncf(zn);
        *(float*)((char*)smem + OFF_ZF + (b * 32 + i) * 4) =
            z_data[z0i * 32 + i] * (1.0f - zl) + z_data[z1i * 32 + i] * zl;
    }
    if (tid < 32) {
        *(float*)((char*)smem + OFF_BB1 + tid * 4) = b1[tid];
        *(float*)((char*)smem + OFF_BB2 + tid * 4) = b2[tid];
        *(float*)((char*)smem + OFF_W3 + tid * 4) = W3[tid];
    }
    if (tid == 0) *(float*)((char*)smem + OFF_B3) = b3[0];
    __syncthreads();   // zf ready

    // ---- Stage 2: build fp16 B fragment tables ----
    // B1 per-batch (zf folded): 8 batches x 8 (kt,nt) x 32 lanes x 8B.
    #pragma unroll
    for (int it = 0; it < 16; it++) {
        const int s = it * 128 + tid;          // 0..2047
        const int ln = s & 31;
        const int e5 = s >> 5;                 // 0..63
        const int e = e5 & 7, b = e5 >> 3;
        const int nt = e & 3, kt = e >> 2;
        const int lg = ln >> 2, lt = ln & 3;
        const int k0 = 16 * kt + 2 * lt;
        const int n  = 8 * nt + lg;
        const float* zfb = (const float*)((char*)smem + OFF_ZF + b * 128);
        const float wa = zfb[k0]     * W1[k0 * 32 + n];
        const float wb = zfb[k0 + 1] * W1[(k0 + 1) * 32 + n];
        const float wc = zfb[k0 + 8] * W1[(k0 + 8) * 32 + n];
        const float wd = zfb[k0 + 9] * W1[(k0 + 9) * 32 + n];
        uint2 v; v.x = pkhf2(wa, wb); v.y = pkhf2(wc, wd);
        *(uint2*)((char*)smem + OFF_B1T + b * 2048 + ((kt * 4 + nt) * 32 + ln) * 8) = v;
    }
    // B2 table (batch-invariant): 8 entries x 32 lanes x 8B.
    #pragma unroll
    for (int it = 0; it < 2; it++) {
        const int s = it * 128 + tid;          // 0..255
        const int ln = s & 31;
        const int e = s >> 5;                  // 0..7
        const int nt = e & 3, kt = e >> 2;
        const int lg = ln >> 2, lt = ln & 3;
        const int k0 = 16 * kt + 2 * lt;
        const int n  = 8 * nt + lg;
        uint2 v;
        v.x = pkhf2(W2[k0 * 32 + n],       W2[(k0 + 1) * 32 + n]);
        v.y = pkhf2(W2[(k0 + 8) * 32 + n], W2[(k0 + 9) * 32 + n]);
        *(uint2*)((char*)smem + OFF_B2T + ((kt * 4 + nt) * 32 + ln) * 8) = v;
    }

    // ---- Bilinear gather -> xy[32], pack (scaled) into per-warp A staging ----
    const int pixbase = blockIdx.x * 128;
    const int p = pixbase + tid;
    const float wx = lerp[2 * p + 0];
    const float wy = lerp[2 * p + 1];
    const int ix0 = x0[p], iy0 = y0[p], ix1 = x1[p], iy1 = y1[p];
    const float4* p00 = (const float4*)(data + (iy0 * 512 + ix0) * 32);
    const float4* p10 = (const float4*)(data + (iy0 * 512 + ix1) * 32);
    const float4* p01 = (const float4*)(data + (iy1 * 512 + ix0) * 32);
    const float4* p11 = (const float4*)(data + (iy1 * 512 + ix1) * 32);
    const float w00 = (1.0f - wx) * (1.0f - wy);
    const float w10 = wx * (1.0f - wy);
    const float w01 = (1.0f - wx) * wy;
    const float w11 = wx * wy;
    float xy[32];
    #pragma unroll
    for (int q = 0; q < 8; q++) {
        const float4 a = p00[q];
        const float4 c = p10[q];
        const float4 e = p01[q];
        const float4 gg = p11[q];
        xy[4 * q + 0] = a.x * w00 + c.x * w10 + e.x * w01 + gg.x * w11;
        xy[4 * q + 1] = a.y * w00 + c.y * w10 + e.y * w01 + gg.y * w11;
        xy[4 * q + 2] = a.z * w00 + c.z * w10 + e.z * w01 + gg.z * w11;
        xy[4 * q + 3] = a.w * w00 + c.w * w10 + e.w * w01 + gg.w * w11;
    }
    const uint32_t aX  = sb + OFF_AST + warp * 4608;
    const uint32_t myX = aX + lane * ROWSTR;
    #pragma unroll
    for (int c = 0; c < 4; c++) {
        uint32_t hw[4], lw[4];
        #pragma unroll
        for (int j = 0; j < 4; j++) {
            const int col = 2 * c + 8 * j;
            const float v0 = xy[col] * SX;
            const float v1 = xy[col + 1] * SX;
            const uint32_t hp = pkhf2(v0, v1);
            hw[j] = hp;
            lw[j] = pkhf2(v0 - lo16h(hp), v1 - hi16h(hp));
        }
        sts128u(myX + c * 32,      hw[0], lw[0], hw[1], lw[1]);
        sts128u(myX + c * 32 + 16, hw[2], lw[2], hw[3], lw[3]);
    }
    __syncthreads();   // tables + staging ready

    // ---- Batch-invariant register state ----
    uint32_t xh[2][2][4], xl[2][2][4];
    #pragma unroll
    for (int mt = 0; mt < 2; mt++) {
        const uint32_t r0 = aX + (mt * 16 + g) * ROWSTR + t * 32;
        const uint32_t r1 = aX + (mt * 16 + g + 8) * ROWSTR + t * 32;
        const uint4 A0k0 = lds128u(r0);
        const uint4 A1k0 = lds128u(r1);
        const uint4 A0k1 = lds128u(r0 + 16);
        const uint4 A1k1 = lds128u(r1 + 16);
        xh[mt][0][0] = A0k0.x; xh[mt][0][1] = A1k0.x; xh[mt][0][2] = A0k0.z; xh[mt][0][3] = A1k0.z;
        xl[mt][0][0] = A0k0.y; xl[mt][0][1] = A1k0.y; xl[mt][0][2] = A0k0.w; xl[mt][0][3] = A1k0.w;
        xh[mt][1][0] = A0k1.x; xh[mt][1][1] = A1k1.x; xh[mt][1][2] = A0k1.z; xh[mt][1][3] = A1k1.z;
        xl[mt][1][0] = A0k1.y; xl[mt][1][1] = A1k1.y; xl[mt][1][2] = A0k1.w; xl[mt][1][3] = A1k1.w;
    }
    uint2 bR2[8];
    #pragma unroll
    for (int e = 0; e < 8; e++)
        bR2[e] = *(const uint2*)((char*)smem + OFF_B2T + (e * 32 + lane) * 8);
    // Bias fragments: bb1 pre-scaled by SH (epilogue-1 works in H*SH domain).
    float2 bb1[4], bb2[4], ww3[4];
    #pragma unroll
    for (int nt = 0; nt < 4; nt++) {
        float2 v = *(const float2*)((char*)smem + OFF_BB1 + (nt * 8 + 2 * t) * 4);
        v.x *= SH; v.y *= SH;
        bb1[nt] = v;
        bb2[nt] = *(const float2*)((char*)smem + OFF_BB2 + (nt * 8 + 2 * t) * 4);
        ww3[nt] = *(const float2*)((char*)smem + OFF_W3 + (nt * 8 + 2 * t) * 4);
    }
    const float b3v = *(const float*)((char*)smem + OFF_B3);
    const float sc1 = SH / SX;       // d1 -> H*SH domain
    const float invSH = 1.0f / SH;   // d2 -> real domain

    #pragma unroll 1
    for (int b = 0; b < 8; b++) {
        const uint32_t bT1 = sb + OFF_B1T + b * 2048;

        // ---- GEMM1: D1 = (Xhi+Xlo)*SX @ B1_b  (A split, B single fp16) ----
        float d1[2][4][4];
        #pragma unroll
        for (int mt = 0; mt < 2; mt++)
            #pragma unroll
            for (int nt = 0; nt < 4; nt++)
                #pragma unroll
                for (int m = 0; m < 4; m++) d1[mt][nt][m] = 0.0f;

        #pragma unroll
        for (int kt = 0; kt < 2; kt++) {
            #pragma unroll
            for (int nt = 0; nt < 4; nt++) {
                const uint2 bv = lds64u(bT1 + ((kt * 4 + nt) * 32 + lane) * 8);
                #pragma unroll
                for (int mt = 0; mt < 2; mt++) {
                    mma_f16(d1[mt][nt], xh[mt][kt], bv.x, bv.y);
                    mma_f16(d1[mt][nt], xl[mt][kt], bv.x, bv.y);
                }
            }
        }

        // ---- Epilogue 1 (regs only): Hs = max(d1*sc1 + b1*SH, 0), split hi/lo
        uint32_t ah[2][2][4], al[2][2][4];
        #pragma unroll
        for (int mt = 0; mt < 2; mt++) {
            #pragma unroll
            for (int nt = 0; nt < 4; nt++) {
                const float* c = d1[mt][nt];
                const int kt = nt >> 1;
                const int ix = (nt & 1) * 2;
                float v0 = fmaxf(fmaf(c[0], sc1, bb1[nt].x), 0.0f);
                float v1 = fmaxf(fmaf(c[1], sc1, bb1[nt].y), 0.0f);
                uint32_t hp = pkhf2(v0, v1);
                ah[mt][kt][ix] = hp;
                al[mt][kt][ix] = pkhf2(v0 - lo16h(hp), v1 - hi16h(hp));
                v0 = fmaxf(fmaf(c[2], sc1, bb1[nt].x), 0.0f);
                v1 = fmaxf(fmaf(c[3], sc1, bb1[nt].y), 0.0f);
                hp = pkhf2(v0, v1);
                ah[mt][kt][ix + 1] = hp;
                al[mt][kt][ix + 1] = pkhf2(v0 - lo16h(hp), v1 - hi16h(hp));
            }
        }

        // ---- GEMM2: D2 = Hs @ B2 (all-register) ----
        float d2[2][4][4];
        #pragma unroll
        for (int mt = 0; mt < 2; mt++)
            #pragma unroll
            for (int nt = 0; nt < 4; nt++)
                #pragma unroll
                for (int m = 0; m < 4; m++) d2[mt][nt][m] = 0.0f;

        #pragma unroll
        for (int kt = 0; kt < 2; kt++) {
            #pragma unroll
            for (int nt = 0; nt < 4; nt++) {
                const uint2 bv = bR2[kt * 4 + nt];
                #pragma unroll
                for (int mt = 0; mt < 2; mt++) {
                    mma_f16(d2[mt][nt], ah[mt][kt], bv.x, bv.y);
                    mma_f16(d2[mt][nt], al[mt][kt], bv.x, bv.y);
                }
            }
        }

        // ---- Epilogue 2: relu(d2/SH + b2) . W3, cross-lane reduce, store ----
        float pr[4] = {0.0f, 0.0f, 0.0f, 0.0f};
        #pragma unroll
        for (int nt = 0; nt < 4; nt++) {
            #pragma unroll
            for (int mt = 0; mt < 2; mt++) {
                const float* dd = d2[mt][nt];
                pr[mt * 2 + 0] = fmaf(fmaxf(fmaf(dd[0], invSH, bb2[nt].x), 0.0f), ww3[nt].x,
                                 fmaf(fmaxf(fmaf(dd[1], invSH, bb2[nt].y), 0.0f), ww3[nt].y, pr[mt * 2 + 0]));
                pr[mt * 2 + 1] = fmaf(fmaxf(fmaf(dd[2], invSH, bb2[nt].x), 0.0f), ww3[nt].x,
                                 fmaf(fmaxf(fmaf(dd[3], invSH, bb2[nt].y), 0.0f), ww3[nt].y, pr[mt * 2 + 1]));
            }
        }
        #pragma unroll
        for (int m = 0; m < 4; m++) {
            pr[m] += __shfl_xor_sync(0xFFFFFFFFu, pr[m], 1);
            pr[m] += __shfl_xor_sync(0xFFFFFFFFu, pr[m], 2);
        }
        if (t == 0) {
            float* ob = out + b * NPIX + pixbase + warp * 32;
            ob[g]          = pr[0] + b3v;
            ob[g + 8]      = pr[1] + b3v;
            ob[16 + g]     = pr[2] + b3v;
            ob[16 + g + 8] = pr[3] + b3v;
        }
    }
}

extern "C" void kernel_launch(void* const* d_in, const int* in_sizes, int n_in,
                              void* d_out, int out_size) {
    const float* z      = (const float*)d_in[0];
    const float* data   = (const float*)d_in[1];
    const float* z_data = (const float*)d_in[2];
    const float* lerp   = (const float*)d_in[3];
    const int*   x0     = (const int*)d_in[4];
    const int*   y0     = (const int*)d_in[5];
    const int*   x1     = (const int*)d_in[6];
    const int*   y1     = (const int*)d_in[7];
    const float* W1     = (const float*)d_in[8];
    const float* b1     = (const float*)d_in[9];
    const float* W2     = (const float*)d_in[10];
    const float* b2     = (const float*)d_in[11];
    const float* W3     = (const float*)d_in[12];
    const float* b3     = (const float*)d_in[13];
    float* out = (float*)d_out;

    cudaFuncSetAttribute(g_tensor3d_mma,
                         cudaFuncAttributeMaxDynamicSharedMemorySize, SMEM_BYTES);

    g_tensor3d_mma<<<NPIX / 128, 128, SMEM_BYTES>>>(z, data, z_data, lerp,
                                                    x0, y0, x1, y1,
                                                    W1, b1, W2, b2, W3, b3, out);
}

// round 17
// speedup vs baseline: 3.2025x; 1.2497x over previous
#include <cuda_runtime.h>
#include <cstdint>

#define NPIX (512*512)

// SMEM byte offsets.
#define OFF_B1T 0       // per-batch B1 frag tables (fp16, zf folded): 8 x 2048B
#define OFF_B2T 16384   // B2 frag table: 2048B
#define OFF_AST 18432   // per-warp X staging (init only): 4 x 4608B
#define OFF_ZF  36864   // zf[8][32] f32 (init only)
#define OFF_BB1 37888
#define OFF_BB2 38016
#define OFF_W3  38144
#define OFF_B3  38272
#define SMEM_BYTES 38400

#define ROWSTR 144
#define SX 4096.0f      // X scale (fp16 range positioning)
#define SH 1024.0f      // H scale

__device__ __forceinline__ uint32_t sptr(const void* p) {
    return (uint32_t)__cvta_generic_to_shared(p);
}
// pack (lo, hi) floats -> fp16x2 (first arg in low half)
__device__ __forceinline__ uint32_t pkhf2(float lo, float hi) {
    uint32_t d;
    asm("cvt.rn.f16x2.f32 %0, %1, %2;" : "=r"(d) : "f"(hi), "f"(lo));
    return d;
}
__device__ __forceinline__ float lo16h(uint32_t p) {
    float f;
    asm("{.reg .b16 a, b;\n\t mov.b32 {a, b}, %1;\n\t cvt.f32.f16 %0, a;}"
        : "=f"(f) : "r"(p));
    return f;
}
__device__ __forceinline__ float hi16h(uint32_t p) {
    float f;
    asm("{.reg .b16 a, b;\n\t mov.b32 {a, b}, %1;\n\t cvt.f32.f16 %0, b;}"
        : "=f"(f) : "r"(p));
    return f;
}

// Volatile shared loads for IN-LOOP data (anti-hoist).
__device__ __forceinline__ uint4 lds128u(uint32_t a) {
    uint4 v;
    asm volatile("ld.shared.v4.b32 {%0,%1,%2,%3}, [%4];"
                 : "=r"(v.x), "=r"(v.y), "=r"(v.z), "=r"(v.w) : "r"(a));
    return v;
}
__device__ __forceinline__ uint2 lds64u(uint32_t a) {
    uint2 v;
    asm volatile("ld.shared.v2.b32 {%0, %1}, [%2];" : "=r"(v.x), "=r"(v.y) : "r"(a));
    return v;
}
__device__ __forceinline__ void sts128u(uint32_t a, uint32_t v0, uint32_t v1,
                                        uint32_t v2, uint32_t v3) {
    asm volatile("st.shared.v4.b32 [%0], {%1,%2,%3,%4};"
                 :: "r"(a), "r"(v0), "r"(v1), "r"(v2), "r"(v3));
}

// Tensor-core MMA, fp16 m16n8k16 with fp32 accum (plain sm_80+ PTX).
__device__ __forceinline__ void mma_f16(float* d, const uint32_t* a,
                                        uint32_t b0, uint32_t b1) {
    asm volatile(
        "mma.sync.aligned.m16n8k16.row.col.f32.f16.f16.f32 "
        "{%0,%1,%2,%3}, {%4,%5,%6,%7}, {%8,%9}, {%0,%1,%2,%3};"
        : "+f"(d[0]), "+f"(d[1]), "+f"(d[2]), "+f"(d[3])
        : "r"(a[0]), "r"(a[1]), "r"(a[2]), "r"(a[3]), "r"(b0), "r"(b1));
}

__global__ __launch_bounds__(128, 4) void g_tensor3d_mma(
    const float* __restrict__ z,
    const float* __restrict__ data,
    const float* __restrict__ z_data,
    const float* __restrict__ lerp,
    const int*   __restrict__ x0,
    const int*   __restrict__ y0,
    const int*   __restrict__ x1,
    const int*   __restrict__ y1,
    const float* __restrict__ W1,
    const float* __restrict__ b1,
    const float* __restrict__ W2,
    const float* __restrict__ b2,
    const float* __restrict__ W3,
    const float* __restrict__ b3,
    float*       __restrict__ out)
{
    extern __shared__ float smem[];
    const uint32_t sb = sptr(smem);
    const int tid = threadIdx.x;
    const int lane = tid & 31;
    const int warp = tid >> 5;
    const int g = lane >> 2, t = lane & 3;

    // ---- Stage 1: z features into SMEM ----
    #pragma unroll
    for (int k = 0; k < 2; k++) {
        const int tt = tid + 128 * k;
        const int b = tt >> 5, i = tt & 31;
        const float zn = 63.0f * z[b];
        int z0i = (int)zn;
        if (z0i < 0) z0i = 0;
        if (z0i > 63) z0i = 63;
        int z1i = z0i + 1;
        if (z1i > 63) z1i = 63;
        const float zl = zn - truncf(zn);
        *(float*)((char*)smem + OFF_ZF + (b * 32 + i) * 4) =
            z_data[z0i * 32 + i] * (1.0f - zl) + z_data[z1i * 32 + i] * zl;
    }
    if (tid < 32) {
        *(float*)((char*)smem + OFF_BB1 + tid * 4) = b1[tid];
        *(float*)((char*)smem + OFF_BB2 + tid * 4) = b2[tid];
        *(float*)((char*)smem + OFF_W3 + tid * 4) = W3[tid];
    }
    if (tid == 0) *(float*)((char*)smem + OFF_B3) = b3[0];
    __syncthreads();   // zf ready

    // ---- Stage 2: build fp16 B fragment tables ----
    // B1 per-batch (zf folded): 8 batches x 8 (kt,nt) x 32 lanes x 8B.
    #pragma unroll
    for (int it = 0; it < 16; it++) {
        const int s = it * 128 + tid;          // 0..2047
        const int ln = s & 31;
        const int e5 = s >> 5;                 // 0..63
        const int e = e5 & 7, b = e5 >> 3;
        const int nt = e & 3, kt = e >> 2;
        const int lg = ln >> 2, lt = ln & 3;
        const int k0 = 16 * kt + 2 * lt;
        const int n  = 8 * nt + lg;
        const float* zfb = (const float*)((char*)smem + OFF_ZF + b * 128);
        const float wa = zfb[k0]     * W1[k0 * 32 + n];
        const float wb = zfb[k0 + 1] * W1[(k0 + 1) * 32 + n];
        const float wc = zfb[k0 + 8] * W1[(k0 + 8) * 32 + n];
        const float wd = zfb[k0 + 9] * W1[(k0 + 9) * 32 + n];
        uint2 v; v.x = pkhf2(wa, wb); v.y = pkhf2(wc, wd);
        *(uint2*)((char*)smem + OFF_B1T + b * 2048 + ((kt * 4 + nt) * 32 + ln) * 8) = v;
    }
    // B2 table (batch-invariant): 8 entries x 32 lanes x 8B.
    #pragma unroll
    for (int it = 0; it < 2; it++) {
        const int s = it * 128 + tid;          // 0..255
        const int ln = s & 31;
        const int e = s >> 5;                  // 0..7
        const int nt = e & 3, kt = e >> 2;
        const int lg = ln >> 2, lt = ln & 3;
        const int k0 = 16 * kt + 2 * lt;
        const int n  = 8 * nt + lg;
        uint2 v;
        v.x = pkhf2(W2[k0 * 32 + n],       W2[(k0 + 1) * 32 + n]);
        v.y = pkhf2(W2[(k0 + 8) * 32 + n], W2[(k0 + 9) * 32 + n]);
        *(uint2*)((char*)smem + OFF_B2T + ((kt * 4 + nt) * 32 + ln) * 8) = v;
    }

    // ---- Bilinear gather -> xy[32], pack (scaled, fp16 hi only) into staging ----
    const int pixbase = blockIdx.x * 128;
    const int p = pixbase + tid;
    const float wx = lerp[2 * p + 0];
    const float wy = lerp[2 * p + 1];
    const int ix0 = x0[p], iy0 = y0[p], ix1 = x1[p], iy1 = y1[p];
    const float4* p00 = (const float4*)(data + (iy0 * 512 + ix0) * 32);
    const float4* p10 = (const float4*)(data + (iy0 * 512 + ix1) * 32);
    const float4* p01 = (const float4*)(data + (iy1 * 512 + ix0) * 32);
    const float4* p11 = (const float4*)(data + (iy1 * 512 + ix1) * 32);
    const float w00 = (1.0f - wx) * (1.0f - wy);
    const float w10 = wx * (1.0f - wy);
    const float w01 = (1.0f - wx) * wy;
    const float w11 = wx * wy;
    float xy[32];
    #pragma unroll
    for (int q = 0; q < 8; q++) {
        const float4 a = p00[q];
        const float4 c = p10[q];
        const float4 e = p01[q];
        const float4 gg = p11[q];
        xy[4 * q + 0] = a.x * w00 + c.x * w10 + e.x * w01 + gg.x * w11;
        xy[4 * q + 1] = a.y * w00 + c.y * w10 + e.y * w01 + gg.y * w11;
        xy[4 * q + 2] = a.z * w00 + c.z * w10 + e.z * w01 + gg.z * w11;
        xy[4 * q + 3] = a.w * w00 + c.w * w10 + e.w * w01 + gg.w * w11;
    }
    const uint32_t aX  = sb + OFF_AST + warp * 4608;
    const uint32_t myX = aX + lane * ROWSTR;
    #pragma unroll
    for (int c = 0; c < 4; c++) {
        uint32_t hw[4];
        #pragma unroll
        for (int j = 0; j < 4; j++) {
            const int col = 2 * c + 8 * j;
            hw[j] = pkhf2(xy[col] * SX, xy[col + 1] * SX);
        }
        // Same layout as R16 (lo slots filled with zeros; never loaded).
        sts128u(myX + c * 32,      hw[0], 0u, hw[1], 0u);
        sts128u(myX + c * 32 + 16, hw[2], 0u, hw[3], 0u);
    }
    __syncthreads();   // tables + staging ready

    // ---- Batch-invariant register state ----
    uint32_t xh[2][2][4];   // [mt][kt][a-reg]
    #pragma unroll
    for (int mt = 0; mt < 2; mt++) {
        const uint32_t r0 = aX + (mt * 16 + g) * ROWSTR + t * 32;
        const uint32_t r1 = aX + (mt * 16 + g + 8) * ROWSTR + t * 32;
        const uint4 A0k0 = lds128u(r0);
        const uint4 A1k0 = lds128u(r1);
        const uint4 A0k1 = lds128u(r0 + 16);
        const uint4 A1k1 = lds128u(r1 + 16);
        xh[mt][0][0] = A0k0.x; xh[mt][0][1] = A1k0.x; xh[mt][0][2] = A0k0.z; xh[mt][0][3] = A1k0.z;
        xh[mt][1][0] = A0k1.x; xh[mt][1][1] = A1k1.x; xh[mt][1][2] = A0k1.z; xh[mt][1][3] = A1k1.z;
    }
    uint2 bR2[8];
    #pragma unroll
    for (int e = 0; e < 8; e++)
        bR2[e] = *(const uint2*)((char*)smem + OFF_B2T + (e * 32 + lane) * 8);
    // Bias fragments: bb1 pre-scaled by SH (epilogue-1 in H*SH domain).
    float2 bb1[4], bb2[4], ww3[4];
    #pragma unroll
    for (int nt = 0; nt < 4; nt++) {
        float2 v = *(const float2*)((char*)smem + OFF_BB1 + (nt * 8 + 2 * t) * 4);
        v.x *= SH; v.y *= SH;
        bb1[nt] = v;
        bb2[nt] = *(const float2*)((char*)smem + OFF_BB2 + (nt * 8 + 2 * t) * 4);
        ww3[nt] = *(const float2*)((char*)smem + OFF_W3 + (nt * 8 + 2 * t) * 4);
    }
    const float b3v = *(const float*)((char*)smem + OFF_B3);
    const float sc1 = SH / SX;       // d1 -> H*SH domain
    const float invSH = 1.0f / SH;   // d2 -> real domain

    #pragma unroll 1
    for (int b = 0; b < 8; b++) {
        const uint32_t bT1 = sb + OFF_B1T + b * 2048;

        // ---- GEMM1: D1 = X*SX @ B1_b (single fp16 both operands) ----
        float d1[2][4][4];
        #pragma unroll
        for (int mt = 0; mt < 2; mt++)
            #pragma unroll
            for (int nt = 0; nt < 4; nt++)
                #pragma unroll
                for (int m = 0; m < 4; m++) d1[mt][nt][m] = 0.0f;

        #pragma unroll
        for (int kt = 0; kt < 2; kt++) {
            #pragma unroll
            for (int nt = 0; nt < 4; nt++) {
                const uint2 bv = lds64u(bT1 + ((kt * 4 + nt) * 32 + lane) * 8);
                #pragma unroll
                for (int mt = 0; mt < 2; mt++)
                    mma_f16(d1[mt][nt], xh[mt][kt], bv.x, bv.y);
            }
        }

        // ---- Epilogue 1 (regs only): Hs = max(d1*sc1 + b1*SH, 0) -> fp16 A frags
        uint32_t ah[2][2][4];
        #pragma unroll
        for (int mt = 0; mt < 2; mt++) {
            #pragma unroll
            for (int nt = 0; nt < 4; nt++) {
                const float* c = d1[mt][nt];
                const int kt = nt >> 1;
                const int ix = (nt & 1) * 2;
                ah[mt][kt][ix] = pkhf2(fmaxf(fmaf(c[0], sc1, bb1[nt].x), 0.0f),
                                       fmaxf(fmaf(c[1], sc1, bb1[nt].y), 0.0f));
                ah[mt][kt][ix + 1] = pkhf2(fmaxf(fmaf(c[2], sc1, bb1[nt].x), 0.0f),
                                           fmaxf(fmaf(c[3], sc1, bb1[nt].y), 0.0f));
            }
        }

        // ---- GEMM2: D2 = Hs @ B2 (all-register) ----
        float d2[2][4][4];
        #pragma unroll
        for (int mt = 0; mt < 2; mt++)
            #pragma unroll
            for (int nt = 0; nt < 4; nt++)
                #pragma unroll
                for (int m = 0; m < 4; m++) d2[mt][nt][m] = 0.0f;

        #pragma unroll
        for (int kt = 0; kt < 2; kt++) {
            #pragma unroll
            for (int nt = 0; nt < 4; nt++) {
                const uint2 bv = bR2[kt * 4 + nt];
                #pragma unroll
                for (int mt = 0; mt < 2; mt++)
                    mma_f16(d2[mt][nt], ah[mt][kt], bv.x, bv.y);
            }
        }

        // ---- Epilogue 2: relu(d2/SH + b2) . W3, cross-lane reduce, store ----
        float pr[4] = {0.0f, 0.0f, 0.0f, 0.0f};
        #pragma unroll
        for (int nt = 0; nt < 4; nt++) {
            #pragma unroll
            for (int mt = 0; mt < 2; mt++) {
                const float* dd = d2[mt][nt];
                pr[mt * 2 + 0] = fmaf(fmaxf(fmaf(dd[0], invSH, bb2[nt].x), 0.0f), ww3[nt].x,
                                 fmaf(fmaxf(fmaf(dd[1], invSH, bb2[nt].y), 0.0f), ww3[nt].y, pr[mt * 2 + 0]));
                pr[mt * 2 + 1] = fmaf(fmaxf(fmaf(dd[2], invSH, bb2[nt].x), 0.0f), ww3[nt].x,
                                 fmaf(fmaxf(fmaf(dd[3], invSH, bb2[nt].y), 0.0f), ww3[nt].y, pr[mt * 2 + 1]));
            }
        }
        #pragma unroll
        for (int m = 0; m < 4; m++) {
            pr[m] += __shfl_xor_sync(0xFFFFFFFFu, pr[m], 1);
            pr[m] += __shfl_xor_sync(0xFFFFFFFFu, pr[m], 2);
        }
        if (t == 0) {
            float* ob = out + b * NPIX + pixbase + warp * 32;
            ob[g]          = pr[0] + b3v;
            ob[g + 8]      = pr[1] + b3v;
            ob[16 + g]     = pr[2] + b3v;
            ob[16 + g + 8] = pr[3] + b3v;
        }
    }
}

extern "C" void kernel_launch(void* const* d_in, const int* in_sizes, int n_in,
                              void* d_out, int out_size) {
    const float* z      = (const float*)d_in[0];
    const float* data   = (const float*)d_in[1];
    const float* z_data = (const float*)d_in[2];
    const float* lerp   = (const float*)d_in[3];
    const int*   x0     = (const int*)d_in[4];
    const int*   y0     = (const int*)d_in[5];
    const int*   x1     = (const int*)d_in[6];
    const int*   y1     = (const int*)d_in[7];
    const float* W1     = (const float*)d_in[8];
    const float* b1     = (const float*)d_in[9];
    const float* W2     = (const float*)d_in[10];
    const float* b2     = (const float*)d_in[11];
    const float* W3     = (const float*)d_in[12];
    const float* b3     = (const float*)d_in[13];
    float* out = (float*)d_out;

    cudaFuncSetAttribute(g_tensor3d_mma,
                         cudaFuncAttributeMaxDynamicSharedMemorySize, SMEM_BYTES);

    g_tensor3d_mma<<<NPIX / 128, 128, SMEM_BYTES>>>(z, data, z_data, lerp,
                                                    x0, y0, x1, y1,
                                                    W1, b1, W2, b2, W3, b3, out);
}